// round 1
// baseline (speedup 1.0000x reference)
#include <cuda_runtime.h>
#include <cstddef>

#define D_    768
#define H_    12
#define DK_   64
#define DFF_  3072
#define L_    12
#define NC_   100
#define S_    512
#define B_    16
#define ROWS  (B_*S_)          // 8192
#define BH_   (B_*H_)          // 192

// ---------------- scratch (static device globals; no allocation) ----------
__device__ float g_x  [ROWS*(size_t)D_];
__device__ float g_q  [ROWS*(size_t)D_];
__device__ float g_k  [ROWS*(size_t)D_];
__device__ float g_v  [ROWS*(size_t)D_];
__device__ float g_ctx[ROWS*(size_t)D_];
__device__ float g_t  [ROWS*(size_t)D_];
__device__ float g_h  [ROWS*(size_t)DFF_];
__device__ float g_sc [(size_t)BH_*S_*S_];
__device__ float g_pool[B_*D_];
__device__ float g_ch  [B_*(D_/2)];

// ---------------- helpers --------------------------------------------------
__device__ __forceinline__ float block_sum(float v) {
    __shared__ float sh[8];
    __shared__ float tot;
    __syncthreads();
    int lane = threadIdx.x & 31, w = threadIdx.x >> 5;
    #pragma unroll
    for (int o = 16; o; o >>= 1) v += __shfl_xor_sync(0xffffffffu, v, o);
    if (lane == 0) sh[w] = v;
    __syncthreads();
    if (w == 0) {
        float t = (lane < 8) ? sh[lane] : 0.f;
        #pragma unroll
        for (int o = 4; o; o >>= 1) t += __shfl_xor_sync(0xffffffffu, t, o);
        if (lane == 0) tot = t;
    }
    __syncthreads();
    return tot;
}

__device__ __forceinline__ float block_max(float v) {
    __shared__ float sh[8];
    __shared__ float tot;
    __syncthreads();
    int lane = threadIdx.x & 31, w = threadIdx.x >> 5;
    #pragma unroll
    for (int o = 16; o; o >>= 1) v = fmaxf(v, __shfl_xor_sync(0xffffffffu, v, o));
    if (lane == 0) sh[w] = v;
    __syncthreads();
    if (w == 0) {
        float t = (lane < 8) ? sh[lane] : -3.4e38f;
        #pragma unroll
        for (int o = 4; o; o >>= 1) t = fmaxf(t, __shfl_xor_sync(0xffffffffu, t, o));
        if (lane == 0) tot = t;
    }
    __syncthreads();
    return tot;
}

// ---------------- embedding + sinusoidal PE --------------------------------
__global__ __launch_bounds__(256) void embed_kernel(
    const int* __restrict__ ids, const float* __restrict__ emb,
    float* __restrict__ x)
{
    int row = blockIdx.x;            // b*S + s
    int s   = row & (S_-1);
    int tok = ids[row];
    size_t base = (size_t)row * D_;
    const float NEG_LOG1E4_OVER_D = -9.210340371976184f / (float)D_;
    #pragma unroll
    for (int i = 0; i < 3; i++) {
        int d = threadIdx.x + i*256;
        int k2 = (d >> 1) << 1;      // 2*(d/2)
        float ang = (float)s * __expf((float)k2 * NEG_LOG1E4_OVER_D);
        float pe  = (d & 1) ? cosf(ang) : sinf(ang);
        x[base + d] = emb[(size_t)tok * D_ + d] + pe;
    }
}

// ---------------- SGEMM: C[M,N] = A[M,K]*W[K,N] + bias, opt ReLU -----------
// BM=128, BN=128, BK=16, 256 threads, 8x8 per thread. M%128==0, N%128==0, K%16==0.
__global__ __launch_bounds__(256) void sgemm_bias(
    const float* __restrict__ A, const float* __restrict__ W,
    const float* __restrict__ bias, float* __restrict__ C,
    int M, int N, int K, int relu)
{
    __shared__ float As[16][128];
    __shared__ float Bs[16][128];
    int tid = threadIdx.x;
    int bx = blockIdx.x;  // N tile
    int by = blockIdx.y;  // M tile
    const float* Ab = A + (size_t)by * 128 * K;
    const float* Wb = W + (size_t)bx * 128;

    int tr = tid >> 4;      // 0..15  (M sub)
    int tc = tid & 15;      // 0..15  (N sub)

    float acc[8][8];
    #pragma unroll
    for (int i = 0; i < 8; i++)
        #pragma unroll
        for (int j = 0; j < 8; j++) acc[i][j] = 0.f;

    int nk = K >> 4;
    for (int kt = 0; kt < nk; kt++) {
        #pragma unroll
        for (int t = 0; t < 2; t++) {
            int idx = tid + t*256;
            int r = idx >> 2, c = (idx & 3) << 2;
            float4 va = *(const float4*)(Ab + (size_t)r * K + kt*16 + c);
            As[c+0][r] = va.x; As[c+1][r] = va.y;
            As[c+2][r] = va.z; As[c+3][r] = va.w;
            int rb = idx >> 5, cb = (idx & 31) << 2;
            float4 vb = *(const float4*)(Wb + (size_t)(kt*16 + rb) * N + cb);
            *(float4*)&Bs[rb][cb] = vb;
        }
        __syncthreads();
        #pragma unroll
        for (int kk = 0; kk < 16; kk++) {
            float4 a0 = *(const float4*)&As[kk][tr*8];
            float4 a1 = *(const float4*)&As[kk][tr*8+4];
            float4 b0 = *(const float4*)&Bs[kk][tc*8];
            float4 b1 = *(const float4*)&Bs[kk][tc*8+4];
            float a[8] = {a0.x,a0.y,a0.z,a0.w,a1.x,a1.y,a1.z,a1.w};
            float b[8] = {b0.x,b0.y,b0.z,b0.w,b1.x,b1.y,b1.z,b1.w};
            #pragma unroll
            for (int i = 0; i < 8; i++)
                #pragma unroll
                for (int j = 0; j < 8; j++) acc[i][j] = fmaf(a[i], b[j], acc[i][j]);
        }
        __syncthreads();
    }

    float bv[8];
    #pragma unroll
    for (int j = 0; j < 8; j++) bv[j] = bias[bx*128 + tc*8 + j];

    #pragma unroll
    for (int i = 0; i < 8; i++) {
        size_t m = (size_t)by*128 + tr*8 + i;
        float out[8];
        #pragma unroll
        for (int j = 0; j < 8; j++) {
            float v = acc[i][j] + bv[j];
            out[j] = relu ? fmaxf(v, 0.f) : v;
        }
        *(float4*)(C + m*N + bx*128 + tc*8)     = make_float4(out[0],out[1],out[2],out[3]);
        *(float4*)(C + m*N + bx*128 + tc*8 + 4) = make_float4(out[4],out[5],out[6],out[7]);
    }
}

// ---------------- attention scores: S = QK^T/8 + rel_bias ------------------
// grid (S/64 key tiles, S/64 query tiles, B*H); 256 threads; 4x4 per thread.
__global__ __launch_bounds__(256) void attn_scores(
    const float* __restrict__ q, const float* __restrict__ k,
    const float* __restrict__ relb, float* __restrict__ sc)
{
    __shared__ float Qs[64][68];   // [dk][query]
    __shared__ float Ks[64][68];   // [dk][key]
    int tid = threadIdx.x;
    int bh = blockIdx.z, b = bh / H_, h = bh % H_;
    int q0 = blockIdx.y * 64, k0 = blockIdx.x * 64;
    const float* qb = q + ((size_t)b*S_ + q0) * D_ + h*DK_;
    const float* kb = k + ((size_t)b*S_ + k0) * D_ + h*DK_;

    #pragma unroll
    for (int t = 0; t < 4; t++) {
        int idx = tid + t*256;
        int r = idx >> 4, c = (idx & 15) << 2;
        float4 vq = *(const float4*)(qb + (size_t)r * D_ + c);
        Qs[c+0][r]=vq.x; Qs[c+1][r]=vq.y; Qs[c+2][r]=vq.z; Qs[c+3][r]=vq.w;
        float4 vk = *(const float4*)(kb + (size_t)r * D_ + c);
        Ks[c+0][r]=vk.x; Ks[c+1][r]=vk.y; Ks[c+2][r]=vk.z; Ks[c+3][r]=vk.w;
    }
    __syncthreads();

    int ty = tid >> 4, tx = tid & 15;
    float acc[4][4] = {};
    #pragma unroll 8
    for (int kk = 0; kk < 64; kk++) {
        float4 a4 = *(const float4*)&Qs[kk][ty*4];
        float4 b4 = *(const float4*)&Ks[kk][tx*4];
        float a[4] = {a4.x,a4.y,a4.z,a4.w};
        float bb[4] = {b4.x,b4.y,b4.z,b4.w};
        #pragma unroll
        for (int i = 0; i < 4; i++)
            #pragma unroll
            for (int j = 0; j < 4; j++) acc[i][j] = fmaf(a[i], bb[j], acc[i][j]);
    }

    #pragma unroll
    for (int i = 0; i < 4; i++) {
        int qg = q0 + ty*4 + i;
        size_t rowbase = ((size_t)bh * S_ + qg) * S_;
        #pragma unroll
        for (int j = 0; j < 4; j++) {
            int kg = k0 + tx*4 + j;
            int ridx = kg - qg + (S_ - 1);                // in [0, 2S-2], no clamp hit
            sc[rowbase + kg] = acc[i][j] * 0.125f + relb[(size_t)ridx * H_ + h];
        }
    }
}

// ---------------- softmax over last dim (512), in place --------------------
__global__ __launch_bounds__(256) void softmax512(float* __restrict__ sc)
{
    size_t base = (size_t)blockIdx.x * S_;
    int tid = threadIdx.x;
    float2 v = *(float2*)(sc + base + tid*2);
    float M = block_max(fmaxf(v.x, v.y));
    float e0 = __expf(v.x - M), e1 = __expf(v.y - M);
    float inv = 1.f / block_sum(e0 + e1);
    *(float2*)(sc + base + tid*2) = make_float2(e0*inv, e1*inv);
}

// ---------------- ctx = P @ V ---------------------------------------------
// grid (S/64 query tiles, B*H); 256 threads; 4x4 per thread; loop K=512/64.
__global__ __launch_bounds__(256) void attn_pv(
    const float* __restrict__ sc, const float* __restrict__ v,
    float* __restrict__ ctx)
{
    __shared__ float Ps[64][68];   // [key][query]
    __shared__ float Vs[64][68];   // [key][dk]
    int tid = threadIdx.x;
    int bh = blockIdx.y, b = bh / H_, h = bh % H_;
    int q0 = blockIdx.x * 64;
    int ty = tid >> 4, tx = tid & 15;
    float acc[4][4] = {};

    for (int kc = 0; kc < S_/64; kc++) {
        int k0 = kc * 64;
        #pragma unroll
        for (int t = 0; t < 4; t++) {
            int idx = tid + t*256;
            int r = idx >> 4, c = (idx & 15) << 2;
            float4 vp = *(const float4*)(sc + ((size_t)bh*S_ + q0 + r)*S_ + k0 + c);
            Ps[c+0][r]=vp.x; Ps[c+1][r]=vp.y; Ps[c+2][r]=vp.z; Ps[c+3][r]=vp.w;
            float4 vv = *(const float4*)(v + ((size_t)b*S_ + k0 + r)*D_ + h*DK_ + c);
            *(float4*)&Vs[r][c] = vv;
        }
        __syncthreads();
        #pragma unroll 8
        for (int kk = 0; kk < 64; kk++) {
            float4 a4 = *(const float4*)&Ps[kk][ty*4];
            float4 b4 = *(const float4*)&Vs[kk][tx*4];
            float a[4] = {a4.x,a4.y,a4.z,a4.w};
            float bb[4] = {b4.x,b4.y,b4.z,b4.w};
            #pragma unroll
            for (int i = 0; i < 4; i++)
                #pragma unroll
                for (int j = 0; j < 4; j++) acc[i][j] = fmaf(a[i], bb[j], acc[i][j]);
        }
        __syncthreads();
    }

    #pragma unroll
    for (int i = 0; i < 4; i++) {
        size_t obase = ((size_t)b*S_ + q0 + ty*4 + i) * D_ + h*DK_ + tx*4;
        *(float4*)(ctx + obase) = make_float4(acc[i][0],acc[i][1],acc[i][2],acc[i][3]);
    }
}

// ---------------- x = LayerNorm(x + t) * g + b (in place on x) -------------
__global__ __launch_bounds__(256) void add_ln(
    float* __restrict__ x, const float* __restrict__ t,
    const float* __restrict__ g, const float* __restrict__ bb)
{
    int row = blockIdx.x, tid = threadIdx.x;
    size_t base = (size_t)row * D_;
    float v[3], s = 0.f;
    #pragma unroll
    for (int i = 0; i < 3; i++) {
        int c = tid + i*256;
        v[i] = x[base+c] + t[base+c];
        s += v[i];
    }
    float mean = block_sum(s) * (1.f/(float)D_);
    float ss = 0.f;
    #pragma unroll
    for (int i = 0; i < 3; i++) { float d = v[i]-mean; ss += d*d; }
    float rstd = rsqrtf(block_sum(ss) * (1.f/(float)D_) + 1e-5f);
    #pragma unroll
    for (int i = 0; i < 3; i++) {
        int c = tid + i*256;
        x[base+c] = (v[i]-mean) * rstd * g[c] + bb[c];
    }
}

// ---------------- mean pool over S ----------------------------------------
__global__ __launch_bounds__(256) void meanpool(
    const float* __restrict__ x, float* __restrict__ pool)
{
    int d = blockIdx.x*256 + threadIdx.x;
    int b = blockIdx.y;
    float s = 0.f;
    for (int t = 0; t < S_; t++) s += x[((size_t)b*S_ + t)*D_ + d];
    pool[b*D_ + d] = s * (1.f/(float)S_);
}

// ---------------- classifier head -----------------------------------------
__global__ __launch_bounds__(256) void fc1(
    const float* __restrict__ pool, const float* __restrict__ w,
    const float* __restrict__ bias, float* __restrict__ out)
{
    int idx = blockIdx.x*256 + threadIdx.x;     // 16*384
    int b = idx / (D_/2), j = idx % (D_/2);
    float s = bias[j];
    for (int d = 0; d < D_; d++) s = fmaf(pool[b*D_ + d], w[d*(D_/2) + j], s);
    out[idx] = fmaxf(s, 0.f);
}

__global__ __launch_bounds__(256) void fc2(
    const float* __restrict__ h, const float* __restrict__ w,
    const float* __restrict__ bias, float* __restrict__ out)
{
    int idx = blockIdx.x*256 + threadIdx.x;     // 16*100
    if (idx >= B_*NC_) return;
    int b = idx / NC_, c = idx % NC_;
    float s = bias[c];
    for (int j = 0; j < D_/2; j++) s = fmaf(h[b*(D_/2) + j], w[j*NC_ + c], s);
    out[idx] = s;
}

// ---------------- launch ---------------------------------------------------
extern "C" void kernel_launch(void* const* d_in, const int* in_sizes, int n_in,
                              void* d_out, int out_size)
{
    const int*   ids  = (const int*)  d_in[0];
    const float* emb  = (const float*)d_in[1];
    const float* wq   = (const float*)d_in[2];
    const float* bq   = (const float*)d_in[3];
    const float* wk   = (const float*)d_in[4];
    const float* bk   = (const float*)d_in[5];
    const float* wv   = (const float*)d_in[6];
    const float* bv   = (const float*)d_in[7];
    const float* wo   = (const float*)d_in[8];
    const float* bo   = (const float*)d_in[9];
    const float* relb = (const float*)d_in[10];
    const float* w1   = (const float*)d_in[11];
    const float* b1   = (const float*)d_in[12];
    const float* w2   = (const float*)d_in[13];
    const float* b2   = (const float*)d_in[14];
    const float* l1g  = (const float*)d_in[15];
    const float* l1b  = (const float*)d_in[16];
    const float* l2g  = (const float*)d_in[17];
    const float* l2b  = (const float*)d_in[18];
    const float* cw1  = (const float*)d_in[19];
    const float* cb1  = (const float*)d_in[20];
    const float* cw2  = (const float*)d_in[21];
    const float* cb2  = (const float*)d_in[22];

    float *x,*q,*k,*v,*ctx,*t,*hbuf,*sc,*pool,*ch;
    cudaGetSymbolAddress((void**)&x,   g_x);
    cudaGetSymbolAddress((void**)&q,   g_q);
    cudaGetSymbolAddress((void**)&k,   g_k);
    cudaGetSymbolAddress((void**)&v,   g_v);
    cudaGetSymbolAddress((void**)&ctx, g_ctx);
    cudaGetSymbolAddress((void**)&t,   g_t);
    cudaGetSymbolAddress((void**)&hbuf,g_h);
    cudaGetSymbolAddress((void**)&sc,  g_sc);
    cudaGetSymbolAddress((void**)&pool,g_pool);
    cudaGetSymbolAddress((void**)&ch,  g_ch);

    embed_kernel<<<ROWS, 256>>>(ids, emb, x);

    for (int l = 0; l < L_; l++) {
        const float* Wq = wq + (size_t)l*D_*D_;
        const float* Wk = wk + (size_t)l*D_*D_;
        const float* Wv = wv + (size_t)l*D_*D_;
        const float* Wo = wo + (size_t)l*D_*D_;
        const float* W1 = w1 + (size_t)l*D_*DFF_;
        const float* W2 = w2 + (size_t)l*DFF_*D_;
        const float* Rb = relb + (size_t)l*(2*S_-1)*H_;

        dim3 gQKV(D_/128, ROWS/128);
        sgemm_bias<<<gQKV, 256>>>(x, Wq, bq + l*D_, q, ROWS, D_, D_, 0);
        sgemm_bias<<<gQKV, 256>>>(x, Wk, bk + l*D_, k, ROWS, D_, D_, 0);
        sgemm_bias<<<gQKV, 256>>>(x, Wv, bv + l*D_, v, ROWS, D_, D_, 0);

        attn_scores<<<dim3(S_/64, S_/64, BH_), 256>>>(q, k, Rb, sc);
        softmax512<<<BH_*S_, 256>>>(sc);
        attn_pv<<<dim3(S_/64, BH_), 256>>>(sc, v, ctx);

        sgemm_bias<<<gQKV, 256>>>(ctx, Wo, bo + l*D_, t, ROWS, D_, D_, 0);
        add_ln<<<ROWS, 256>>>(x, t, l1g + l*D_, l1b + l*D_);

        sgemm_bias<<<dim3(DFF_/128, ROWS/128), 256>>>(x, W1, b1 + l*DFF_, hbuf, ROWS, DFF_, D_, 1);
        sgemm_bias<<<dim3(D_/128, ROWS/128), 256>>>(hbuf, W2, b2 + l*D_, t, ROWS, D_, DFF_, 0);
        add_ln<<<ROWS, 256>>>(x, t, l2g + l*D_, l2b + l*D_);
    }

    meanpool<<<dim3(D_/256, B_), 256>>>(x, pool);
    fc1<<<(B_*(D_/2))/256, 256>>>(pool, cw1, cb1, ch);
    fc2<<<(B_*NC_ + 255)/256, 256>>>(ch, cw2, cb2, (float*)d_out);
}

// round 4
// speedup vs baseline: 2.0398x; 2.0398x over previous
#include <cuda_runtime.h>
#include <cuda_bf16.h>
#include <cstdint>
#include <cstddef>

#define D_    768
#define H_    12
#define DK_   64
#define DFF_  3072
#define L_    12
#define NC_   100
#define S_    512
#define B_    16
#define ROWS  (B_*S_)          // 8192
#define BH_   (B_*H_)          // 192

typedef __nv_bfloat16 bf16;

// ---------------- scratch (static device globals; no allocation) ----------
__device__ __align__(256) float g_x  [ROWS*(size_t)D_];
__device__ __align__(256) float g_t  [ROWS*(size_t)D_];
__device__ __align__(256) bf16  g_xh [ROWS*(size_t)D_];
__device__ __align__(256) bf16  g_xl [ROWS*(size_t)D_];
__device__ __align__(256) bf16  g_qh [ROWS*(size_t)D_];
__device__ __align__(256) bf16  g_ql [ROWS*(size_t)D_];
__device__ __align__(256) bf16  g_kh [ROWS*(size_t)D_];
__device__ __align__(256) bf16  g_kl [ROWS*(size_t)D_];
__device__ __align__(256) bf16  g_vh [ROWS*(size_t)D_];
__device__ __align__(256) bf16  g_vl [ROWS*(size_t)D_];
__device__ __align__(256) bf16  g_vth[ROWS*(size_t)D_];   // [bh][dk][s]
__device__ __align__(256) bf16  g_vtl[ROWS*(size_t)D_];
__device__ __align__(256) bf16  g_cxh[ROWS*(size_t)D_];
__device__ __align__(256) bf16  g_cxl[ROWS*(size_t)D_];
__device__ __align__(256) bf16  g_fh [ROWS*(size_t)DFF_];
__device__ __align__(256) bf16  g_fl [ROWS*(size_t)DFF_];
__device__ __align__(256) float g_sc [(size_t)BH_*S_*S_];
__device__ __align__(256) bf16  g_ph [(size_t)BH_*S_*S_];
__device__ __align__(256) bf16  g_pl [(size_t)BH_*S_*S_];
__device__ __align__(256) bf16  g_wth[(size_t)DFF_*D_];   // [N][K] weight hi
__device__ __align__(256) bf16  g_wtl[(size_t)DFF_*D_];
__device__ __align__(256) float g_pool[B_*D_];
__device__ __align__(256) float g_chd [B_*(D_/2)];

// ---------------- helpers ---------------------------------------------------
__device__ __forceinline__ uint32_t smem_u32(const void* p) {
    uint32_t a;
    asm("{ .reg .u64 t; cvta.to.shared.u64 t, %1; cvt.u32.u64 %0, t; }" : "=r"(a) : "l"(p));
    return a;
}
__device__ __forceinline__ void split_bf16(float v, bf16& h, bf16& l) {
    h = __float2bfloat16(v);
    l = __float2bfloat16(v - __bfloat162float(h));
}
__device__ __forceinline__ void ldsm4(uint32_t* r, uint32_t a) {
    asm volatile("ldmatrix.sync.aligned.m8n8.x4.shared.b16 {%0,%1,%2,%3}, [%4];"
        : "=r"(r[0]), "=r"(r[1]), "=r"(r[2]), "=r"(r[3]) : "r"(a));
}
__device__ __forceinline__ void mma16816(float* c, const uint32_t* a, const uint32_t* b) {
    asm volatile("mma.sync.aligned.m16n8k16.row.col.f32.bf16.bf16.f32 "
        "{%0,%1,%2,%3}, {%4,%5,%6,%7}, {%8,%9}, {%0,%1,%2,%3};"
        : "+f"(c[0]), "+f"(c[1]), "+f"(c[2]), "+f"(c[3])
        : "r"(a[0]), "r"(a[1]), "r"(a[2]), "r"(a[3]), "r"(b[0]), "r"(b[1]));
}

__device__ __forceinline__ float block_sum(float v) {
    __shared__ float sh[8]; __shared__ float tot;
    __syncthreads();
    int lane = threadIdx.x & 31, w = threadIdx.x >> 5;
    #pragma unroll
    for (int o = 16; o; o >>= 1) v += __shfl_xor_sync(0xffffffffu, v, o);
    if (lane == 0) sh[w] = v;
    __syncthreads();
    if (w == 0) {
        float t = (lane < 8) ? sh[lane] : 0.f;
        #pragma unroll
        for (int o = 4; o; o >>= 1) t += __shfl_xor_sync(0xffffffffu, t, o);
        if (lane == 0) tot = t;
    }
    __syncthreads();
    return tot;
}
__device__ __forceinline__ float block_max(float v) {
    __shared__ float sh[8]; __shared__ float tot;
    __syncthreads();
    int lane = threadIdx.x & 31, w = threadIdx.x >> 5;
    #pragma unroll
    for (int o = 16; o; o >>= 1) v = fmaxf(v, __shfl_xor_sync(0xffffffffu, v, o));
    if (lane == 0) sh[w] = v;
    __syncthreads();
    if (w == 0) {
        float t = (lane < 8) ? sh[lane] : -3.4e38f;
        #pragma unroll
        for (int o = 4; o; o >>= 1) t = fmaxf(t, __shfl_xor_sync(0xffffffffu, t, o));
        if (lane == 0) tot = t;
    }
    __syncthreads();
    return tot;
}

// ---------------- embedding + PE -------------------------------------------
__global__ __launch_bounds__(256) void embed_kernel(
    const int* __restrict__ ids, const float* __restrict__ emb,
    float* __restrict__ x, bf16* __restrict__ xh, bf16* __restrict__ xl)
{
    int row = blockIdx.x;
    int s   = row & (S_-1);
    int tok = ids[row];
    size_t base = (size_t)row * D_;
    const float NEG = -9.210340371976184f / (float)D_;
    #pragma unroll
    for (int i = 0; i < 3; i++) {
        int d = threadIdx.x + i*256;
        int k2 = (d >> 1) << 1;
        float ang = (float)s * __expf((float)k2 * NEG);
        float pe  = (d & 1) ? cosf(ang) : sinf(ang);
        float v = emb[(size_t)tok * D_ + d] + pe;
        x[base + d] = v;
        bf16 h, l; split_bf16(v, h, l);
        xh[base + d] = h; xl[base + d] = l;
    }
}

// ---------------- weight prep: W[K,N] fp32 -> Wt[N][K] hi/lo ----------------
__global__ __launch_bounds__(256) void wprep(
    const float* __restrict__ W, bf16* __restrict__ Th, bf16* __restrict__ Tl,
    int K, int N)
{
    __shared__ float t[32][33];
    int tx = threadIdx.x & 31, ty = threadIdx.x >> 5;
    int n0 = blockIdx.x * 32, k0 = blockIdx.y * 32;
    #pragma unroll
    for (int i = ty; i < 32; i += 8)
        t[i][tx] = W[(size_t)(k0 + i) * N + n0 + tx];
    __syncthreads();
    #pragma unroll
    for (int i = ty; i < 32; i += 8) {
        float v = t[tx][i];
        bf16 h, l; split_bf16(v, h, l);
        size_t o = (size_t)(n0 + i) * K + k0 + tx;
        Th[o] = h; Tl[o] = l;
    }
}

// ---------------- V transpose: v[rows,768] -> vt[bh][dk][s] -----------------
__global__ __launch_bounds__(256) void vtrans(
    const bf16* __restrict__ vh, const bf16* __restrict__ vl,
    bf16* __restrict__ vth, bf16* __restrict__ vtl)
{
    __shared__ bf16 th[32][33], tl[32][33];
    int tx = threadIdx.x & 31, ty = threadIdx.x >> 5;
    int s0 = blockIdx.x * 32, d0 = blockIdx.y * 32;
    int bh = blockIdx.z, b = bh / H_, h = bh % H_;
    #pragma unroll
    for (int i = ty; i < 32; i += 8) {
        size_t src = (size_t)(b*S_ + s0 + i) * D_ + h*DK_ + d0 + tx;
        th[i][tx] = vh[src]; tl[i][tx] = vl[src];
    }
    __syncthreads();
    #pragma unroll
    for (int i = ty; i < 32; i += 8) {
        size_t dst = (size_t)(bh*DK_ + d0 + i) * S_ + s0 + tx;
        vth[dst] = th[tx][i]; vtl[dst] = tl[tx][i];
    }
}

// ---------------- generic warp-MMA GEMM -------------------------------------
// C[128x128 tile] = A[M,K] (hi/lo) x B[N,K]^T (hi/lo), 3-pass emulated fp32.
// modes: 0 fp32+bias | 1 split+bias | 2 relu+split+bias | 3 scores | 4 split noBias (col guard)
#define ROWB  80
#define TILEB (128*ROWB)
#define BUFB  (4*TILEB)
#define GSMEM (2*BUFB)        // 81920

__global__ __launch_bounds__(256) void gemm_mma(
    const bf16* __restrict__ Ah, const bf16* __restrict__ Al,
    unsigned long long aSB, unsigned long long aSH, int lda,
    const bf16* __restrict__ Bh, const bf16* __restrict__ Bl,
    unsigned long long bSB, unsigned long long bSH, int ldb,
    const float* __restrict__ bias, const float* __restrict__ relb,
    float* __restrict__ Cf, bf16* __restrict__ Ch, bf16* __restrict__ Cl,
    unsigned long long cSB, unsigned long long cSH, int ldo,
    int N, int K, int mode)
{
    extern __shared__ char sm[];
    uint32_t sb = smem_u32(sm);
    int tid = threadIdx.x, lane = tid & 31, wid = tid >> 5;
    int bx = blockIdx.x, by = blockIdx.y, bz = blockIdx.z;
    int b_ = bz / H_, h_ = bz % H_;
    const bf16* pAh = Ah + (size_t)b_*aSB + (size_t)h_*aSH;
    const bf16* pAl = Al + (size_t)b_*aSB + (size_t)h_*aSH;
    const bf16* pBh = Bh + (size_t)b_*bSB + (size_t)h_*bSH;
    const bf16* pBl = Bl + (size_t)b_*bSB + (size_t)h_*bSH;
    int wm = wid & 3, wn = wid >> 2;

    float acc[2][8][4];
    #pragma unroll
    for (int i = 0; i < 2; i++)
        #pragma unroll
        for (int j = 0; j < 8; j++)
            #pragma unroll
            for (int q = 0; q < 4; q++) acc[i][j][q] = 0.f;

    uint32_t aoffs = (uint32_t)((wm*32 + (lane & 15))*ROWB) + (((uint32_t)lane >> 4) << 4);
    uint32_t boffs = (uint32_t)((wn*64 + (lane & 7) + ((lane >> 4) << 3))*ROWB)
                   + ((((uint32_t)lane >> 3) & 1) << 4);

    int nch = K >> 5;

    auto load_chunk = [&](int kt, int bufi) {
        int k0 = kt << 5;
        uint32_t dbase = sb + bufi*BUFB;
        #pragma unroll
        for (int i = 0; i < 8; i++) {
            int idx = tid + (i << 8);
            int tile = idx >> 9;
            int r = (idx >> 2) & 127;
            int c = idx & 3;
            uint32_t dst = dbase + tile*TILEB + r*ROWB + (c << 4);
            if (tile == 0) {
                const bf16* s = pAh + (size_t)(by*128 + r)*lda + k0 + c*8;
                asm volatile("cp.async.cg.shared.global [%0], [%1], 16;" :: "r"(dst), "l"(s));
            } else if (tile == 1) {
                const bf16* s = pAl + (size_t)(by*128 + r)*lda + k0 + c*8;
                asm volatile("cp.async.cg.shared.global [%0], [%1], 16;" :: "r"(dst), "l"(s));
            } else {
                int n = bx*128 + r;
                int nc = n < N ? n : 0;
                const bf16* s = (tile == 2 ? pBh : pBl) + (size_t)nc*ldb + k0 + c*8;
                uint32_t sz = (n < N) ? 16u : 0u;
                asm volatile("cp.async.cg.shared.global [%0], [%1], 16, %2;"
                             :: "r"(dst), "l"(s), "r"(sz));
            }
        }
        asm volatile("cp.async.commit_group;" ::: "memory");
    };

    load_chunk(0, 0);
    for (int kt = 0; kt < nch; kt++) {
        int bufi = kt & 1;
        if (kt + 1 < nch) {
            load_chunk(kt + 1, bufi ^ 1);
            asm volatile("cp.async.wait_group 1;" ::: "memory");
        } else {
            asm volatile("cp.async.wait_group 0;" ::: "memory");
        }
        __syncthreads();
        uint32_t base = sb + bufi*BUFB;
        #pragma unroll
        for (int ks = 0; ks < 2; ks++) {
            uint32_t kb = (uint32_t)ks << 5;
            uint32_t aH[2][4], aL[2][4], bH[4][4], bL[4][4];
            #pragma unroll
            for (int mt = 0; mt < 2; mt++)
                ldsm4(aH[mt], base + aoffs + mt*(16*ROWB) + kb);
            #pragma unroll
            for (int p = 0; p < 4; p++)
                ldsm4(bH[p], base + 2*TILEB + boffs + p*(16*ROWB) + kb);
            #pragma unroll
            for (int mt = 0; mt < 2; mt++)
                #pragma unroll
                for (int nt = 0; nt < 8; nt++)
                    mma16816(acc[mt][nt], aH[mt], &bH[nt >> 1][(nt & 1) << 1]);
            #pragma unroll
            for (int p = 0; p < 4; p++)
                ldsm4(bL[p], base + 3*TILEB + boffs + p*(16*ROWB) + kb);
            #pragma unroll
            for (int mt = 0; mt < 2; mt++)
                #pragma unroll
                for (int nt = 0; nt < 8; nt++)
                    mma16816(acc[mt][nt], aH[mt], &bL[nt >> 1][(nt & 1) << 1]);
            #pragma unroll
            for (int mt = 0; mt < 2; mt++)
                ldsm4(aL[mt], base + TILEB + aoffs + mt*(16*ROWB) + kb);
            #pragma unroll
            for (int mt = 0; mt < 2; mt++)
                #pragma unroll
                for (int nt = 0; nt < 8; nt++)
                    mma16816(acc[mt][nt], aL[mt], &bH[nt >> 1][(nt & 1) << 1]);
        }
        __syncthreads();
    }

    // ---------------- epilogue ----------------
    size_t cOff = (size_t)b_*cSB + (size_t)h_*cSH;
    #pragma unroll
    for (int mt = 0; mt < 2; mt++) {
        #pragma unroll
        for (int nt = 0; nt < 8; nt++) {
            int rr = by*128 + wm*32 + mt*16 + (lane >> 2);
            int cc = bx*128 + wn*64 + nt*8 + ((lane & 3) << 1);
            #pragma unroll
            for (int hf = 0; hf < 2; hf++) {
                int r = rr + hf*8;
                float v0 = acc[mt][nt][hf*2], v1 = acc[mt][nt][hf*2 + 1];
                size_t o = cOff + (size_t)r*ldo + cc;
                if (mode == 0) {
                    *(float2*)(Cf + o) = make_float2(v0 + bias[cc], v1 + bias[cc + 1]);
                } else if (mode == 3) {
                    float b0 = relb[(size_t)(cc - r + (S_-1))*H_ + h_];
                    float b1 = relb[(size_t)(cc + 1 - r + (S_-1))*H_ + h_];
                    *(float2*)(Cf + o) = make_float2(fmaf(v0, 0.125f, b0),
                                                     fmaf(v1, 0.125f, b1));
                } else {
                    if (mode == 4) { if (cc >= N) continue; }
                    else { v0 += bias[cc]; v1 += bias[cc + 1]; }
                    if (mode == 2) { v0 = fmaxf(v0, 0.f); v1 = fmaxf(v1, 0.f); }
                    bf16 h0, l0, h1, l1;
                    split_bf16(v0, h0, l0); split_bf16(v1, h1, l1);
                    __nv_bfloat162 hv; hv.x = h0; hv.y = h1;
                    __nv_bfloat162 lv; lv.x = l0; lv.y = l1;
                    *(__nv_bfloat162*)(Ch + o) = hv;
                    *(__nv_bfloat162*)(Cl + o) = lv;
                }
            }
        }
    }
}

// ---------------- softmax (fp32 in, bf16 hi/lo out) -------------------------
__global__ __launch_bounds__(256) void softmax512(
    const float* __restrict__ sc, bf16* __restrict__ ph, bf16* __restrict__ pl)
{
    size_t base = (size_t)blockIdx.x * S_;
    int tid = threadIdx.x;
    float2 v = *(const float2*)(sc + base + tid*2);
    float M = block_max(fmaxf(v.x, v.y));
    float e0 = __expf(v.x - M), e1 = __expf(v.y - M);
    float inv = 1.f / block_sum(e0 + e1);
    float p0 = e0*inv, p1 = e1*inv;
    bf16 h0, l0, h1, l1;
    split_bf16(p0, h0, l0); split_bf16(p1, h1, l1);
    ph[base + tid*2] = h0; ph[base + tid*2 + 1] = h1;
    pl[base + tid*2] = l0; pl[base + tid*2 + 1] = l1;
}

// ---------------- x = LayerNorm(x + t); writes fp32 + hi/lo -----------------
__global__ __launch_bounds__(256) void add_ln(
    float* __restrict__ x, const float* __restrict__ t,
    const float* __restrict__ g, const float* __restrict__ bb,
    bf16* __restrict__ xh, bf16* __restrict__ xl)
{
    int row = blockIdx.x, tid = threadIdx.x;
    size_t base = (size_t)row * D_;
    float v[3], s = 0.f;
    #pragma unroll
    for (int i = 0; i < 3; i++) {
        int c = tid + i*256;
        v[i] = x[base+c] + t[base+c];
        s += v[i];
    }
    float mean = block_sum(s) * (1.f/(float)D_);
    float ss = 0.f;
    #pragma unroll
    for (int i = 0; i < 3; i++) { float d = v[i]-mean; ss += d*d; }
    float rstd = rsqrtf(block_sum(ss) * (1.f/(float)D_) + 1e-5f);
    #pragma unroll
    for (int i = 0; i < 3; i++) {
        int c = tid + i*256;
        float o = (v[i]-mean) * rstd * g[c] + bb[c];
        x[base+c] = o;
        bf16 h, l; split_bf16(o, h, l);
        xh[base+c] = h; xl[base+c] = l;
    }
}

// ---------------- head ------------------------------------------------------
__global__ __launch_bounds__(256) void meanpool(
    const float* __restrict__ x, float* __restrict__ pool)
{
    int d = blockIdx.x*256 + threadIdx.x;
    int b = blockIdx.y;
    float s = 0.f;
    for (int t = 0; t < S_; t++) s += x[((size_t)b*S_ + t)*D_ + d];
    pool[b*D_ + d] = s * (1.f/(float)S_);
}
__global__ __launch_bounds__(256) void fc1(
    const float* __restrict__ pool, const float* __restrict__ w,
    const float* __restrict__ bias, float* __restrict__ out)
{
    int idx = blockIdx.x*256 + threadIdx.x;
    int b = idx / (D_/2), j = idx % (D_/2);
    float s = bias[j];
    for (int d = 0; d < D_; d++) s = fmaf(pool[b*D_ + d], w[d*(D_/2) + j], s);
    out[idx] = fmaxf(s, 0.f);
}
__global__ __launch_bounds__(256) void fc2(
    const float* __restrict__ h, const float* __restrict__ w,
    const float* __restrict__ bias, float* __restrict__ out)
{
    int idx = blockIdx.x*256 + threadIdx.x;
    if (idx >= B_*NC_) return;
    int b = idx / NC_, c = idx % NC_;
    float s = bias[c];
    for (int j = 0; j < D_/2; j++) s = fmaf(h[b*(D_/2) + j], w[j*NC_ + c], s);
    out[idx] = s;
}

// ---------------- launch ----------------------------------------------------
extern "C" void kernel_launch(void* const* d_in, const int* in_sizes, int n_in,
                              void* d_out, int out_size)
{
    const int*   ids  = (const int*)  d_in[0];
    const float* emb  = (const float*)d_in[1];
    const float* wq   = (const float*)d_in[2];
    const float* bq   = (const float*)d_in[3];
    const float* wk   = (const float*)d_in[4];
    const float* bk   = (const float*)d_in[5];
    const float* wv   = (const float*)d_in[6];
    const float* bv   = (const float*)d_in[7];
    const float* wo   = (const float*)d_in[8];
    const float* bo   = (const float*)d_in[9];
    const float* relb = (const float*)d_in[10];
    const float* w1   = (const float*)d_in[11];
    const float* b1   = (const float*)d_in[12];
    const float* w2   = (const float*)d_in[13];
    const float* b2   = (const float*)d_in[14];
    const float* l1g  = (const float*)d_in[15];
    const float* l1b  = (const float*)d_in[16];
    const float* l2g  = (const float*)d_in[17];
    const float* l2b  = (const float*)d_in[18];
    const float* cw1  = (const float*)d_in[19];
    const float* cb1  = (const float*)d_in[20];
    const float* cw2  = (const float*)d_in[21];
    const float* cb2  = (const float*)d_in[22];

    cudaFuncSetAttribute(gemm_mma, cudaFuncAttributeMaxDynamicSharedMemorySize, GSMEM);

    float *x, *t, *sc, *pool, *chd;
    bf16 *xh,*xl,*qh,*ql,*kh,*kl,*vh,*vl,*vth,*vtl,*cxh,*cxl,*fh,*fl,*ph,*pl,*wth,*wtl;
    cudaGetSymbolAddress((void**)&x,   g_x);
    cudaGetSymbolAddress((void**)&t,   g_t);
    cudaGetSymbolAddress((void**)&sc,  g_sc);
    cudaGetSymbolAddress((void**)&pool,g_pool);
    cudaGetSymbolAddress((void**)&chd, g_chd);
    cudaGetSymbolAddress((void**)&xh,  g_xh);
    cudaGetSymbolAddress((void**)&xl,  g_xl);
    cudaGetSymbolAddress((void**)&qh,  g_qh);
    cudaGetSymbolAddress((void**)&ql,  g_ql);
    cudaGetSymbolAddress((void**)&kh,  g_kh);
    cudaGetSymbolAddress((void**)&kl,  g_kl);
    cudaGetSymbolAddress((void**)&vh,  g_vh);
    cudaGetSymbolAddress((void**)&vl,  g_vl);
    cudaGetSymbolAddress((void**)&vth, g_vth);
    cudaGetSymbolAddress((void**)&vtl, g_vtl);
    cudaGetSymbolAddress((void**)&cxh, g_cxh);
    cudaGetSymbolAddress((void**)&cxl, g_cxl);
    cudaGetSymbolAddress((void**)&fh,  g_fh);
    cudaGetSymbolAddress((void**)&fl,  g_fl);
    cudaGetSymbolAddress((void**)&ph,  g_ph);
    cudaGetSymbolAddress((void**)&pl,  g_pl);
    cudaGetSymbolAddress((void**)&wth, g_wth);
    cudaGetSymbolAddress((void**)&wtl, g_wtl);

    embed_kernel<<<ROWS, 256>>>(ids, emb, x, xh, xl);

    dim3 wpDD(D_/32, D_/32);
    dim3 wp1(DFF_/32, D_/32);
    dim3 wp2(D_/32, DFF_/32);
    dim3 gDD(D_/128, ROWS/128, 1);
    dim3 gF1(DFF_/128, ROWS/128, 1);
    dim3 gSC(S_/128, S_/128, BH_);
    dim3 gPV(1, S_/128, BH_);

    for (int l = 0; l < L_; l++) {
        const float* Wq = wq + (size_t)l*D_*D_;
        const float* Wk = wk + (size_t)l*D_*D_;
        const float* Wv = wv + (size_t)l*D_*D_;
        const float* Wo = wo + (size_t)l*D_*D_;
        const float* W1 = w1 + (size_t)l*D_*DFF_;
        const float* W2 = w2 + (size_t)l*DFF_*D_;
        const float* Rb = relb + (size_t)l*(2*S_-1)*H_;

        wprep<<<wpDD, 256>>>(Wq, wth, wtl, D_, D_);
        gemm_mma<<<gDD, 256, GSMEM>>>(xh, xl, 0, 0, D_, wth, wtl, 0, 0, D_,
            bq + l*D_, nullptr, nullptr, qh, ql, 0, 0, D_, D_, D_, 1);
        wprep<<<wpDD, 256>>>(Wk, wth, wtl, D_, D_);
        gemm_mma<<<gDD, 256, GSMEM>>>(xh, xl, 0, 0, D_, wth, wtl, 0, 0, D_,
            bk + l*D_, nullptr, nullptr, kh, kl, 0, 0, D_, D_, D_, 1);
        wprep<<<wpDD, 256>>>(Wv, wth, wtl, D_, D_);
        gemm_mma<<<gDD, 256, GSMEM>>>(xh, xl, 0, 0, D_, wth, wtl, 0, 0, D_,
            bv + l*D_, nullptr, nullptr, vh, vl, 0, 0, D_, D_, D_, 1);
        vtrans<<<dim3(S_/32, DK_/32, BH_), 256>>>(vh, vl, vth, vtl);

        // scores: per (b,h): Q[512,64] x K[512,64]^T -> sc[512,512]
        gemm_mma<<<gSC, 256, GSMEM>>>(
            qh, ql, (unsigned long long)S_*D_, DK_, D_,
            kh, kl, (unsigned long long)S_*D_, DK_, D_,
            nullptr, Rb,
            sc, nullptr, nullptr,
            (unsigned long long)H_*S_*S_, (unsigned long long)S_*S_, S_,
            S_, DK_, 3);
        softmax512<<<BH_*S_, 256>>>(sc, ph, pl);
        // PV: per (b,h): P[512,512] x Vt[64,512]^T -> ctx[512,64]
        gemm_mma<<<gPV, 256, GSMEM>>>(
            ph, pl, (unsigned long long)H_*S_*S_, (unsigned long long)S_*S_, S_,
            vth, vtl, (unsigned long long)H_*DK_*S_, (unsigned long long)DK_*S_, S_,
            nullptr, nullptr,
            nullptr, cxh, cxl,
            (unsigned long long)S_*D_, DK_, D_,
            DK_, S_, 4);

        wprep<<<wpDD, 256>>>(Wo, wth, wtl, D_, D_);
        gemm_mma<<<gDD, 256, GSMEM>>>(cxh, cxl, 0, 0, D_, wth, wtl, 0, 0, D_,
            bo + l*D_, nullptr, t, nullptr, nullptr, 0, 0, D_, D_, D_, 0);
        add_ln<<<ROWS, 256>>>(x, t, l1g + l*D_, l1b + l*D_, xh, xl);

        wprep<<<wp1, 256>>>(W1, wth, wtl, D_, DFF_);
        gemm_mma<<<gF1, 256, GSMEM>>>(xh, xl, 0, 0, D_, wth, wtl, 0, 0, D_,
            b1 + l*DFF_, nullptr, nullptr, fh, fl, 0, 0, DFF_, DFF_, D_, 2);
        wprep<<<wp2, 256>>>(W2, wth, wtl, DFF_, D_);
        gemm_mma<<<gDD, 256, GSMEM>>>(fh, fl, 0, 0, DFF_, wth, wtl, 0, 0, DFF_,
            b2 + l*D_, nullptr, t, nullptr, nullptr, 0, 0, D_, D_, DFF_, 0);
        add_ln<<<ROWS, 256>>>(x, t, l2g + l*D_, l2b + l*D_, xh, xl);
    }

    meanpool<<<dim3(D_/256, B_), 256>>>(x, pool);
    fc1<<<(B_*(D_/2))/256, 256>>>(pool, cw1, cb1, chd);
    fc2<<<(B_*NC_ + 255)/256, 256>>>(chd, cw2, cb2, (float*)d_out);
}

// round 5
// speedup vs baseline: 2.1305x; 1.0445x over previous
#include <cuda_runtime.h>
#include <cuda_bf16.h>
#include <cstdint>
#include <cstddef>

#define D_    768
#define H_    12
#define DK_   64
#define DFF_  3072
#define L_    12
#define NC_   100
#define S_    512
#define B_    16
#define ROWS  (B_*S_)          // 8192
#define BH_   (B_*H_)          // 192

typedef __nv_bfloat16 bf16;

// ---------------- scratch (static device globals; no allocation) ----------
__device__ __align__(256) float g_x  [ROWS*(size_t)D_];
__device__ __align__(256) float g_t  [ROWS*(size_t)D_];
__device__ __align__(256) bf16  g_xh [ROWS*(size_t)D_];
__device__ __align__(256) bf16  g_xl [ROWS*(size_t)D_];
__device__ __align__(256) bf16  g_qh [ROWS*(size_t)D_];
__device__ __align__(256) bf16  g_ql [ROWS*(size_t)D_];
__device__ __align__(256) bf16  g_kh [ROWS*(size_t)D_];
__device__ __align__(256) bf16  g_kl [ROWS*(size_t)D_];
__device__ __align__(256) bf16  g_vh [ROWS*(size_t)D_];
__device__ __align__(256) bf16  g_vl [ROWS*(size_t)D_];
__device__ __align__(256) bf16  g_vth[ROWS*(size_t)D_];   // [bh][dk][s]
__device__ __align__(256) bf16  g_vtl[ROWS*(size_t)D_];
__device__ __align__(256) bf16  g_cxh[ROWS*(size_t)D_];
__device__ __align__(256) bf16  g_cxl[ROWS*(size_t)D_];
__device__ __align__(256) bf16  g_fh [ROWS*(size_t)DFF_];
__device__ __align__(256) bf16  g_fl [ROWS*(size_t)DFF_];
__device__ __align__(256) float g_sc [(size_t)BH_*S_*S_];
__device__ __align__(256) bf16  g_ph [(size_t)BH_*S_*S_];
__device__ __align__(256) bf16  g_pl [(size_t)BH_*S_*S_];
// pre-split transposed weights for ALL layers
__device__ __align__(256) bf16  g_wqkh[(size_t)L_*4*D_*D_];  // [l][m][N=768][K=768]
__device__ __align__(256) bf16  g_wqkl[(size_t)L_*4*D_*D_];
__device__ __align__(256) bf16  g_w1h [(size_t)L_*DFF_*D_];  // [l][N=3072][K=768]
__device__ __align__(256) bf16  g_w1l [(size_t)L_*DFF_*D_];
__device__ __align__(256) bf16  g_w2h [(size_t)L_*DFF_*D_];  // [l][N=768][K=3072]
__device__ __align__(256) bf16  g_w2l [(size_t)L_*DFF_*D_];
__device__ __align__(256) float g_pool[B_*D_];
__device__ __align__(256) float g_chd [B_*(D_/2)];

// ---------------- helpers ---------------------------------------------------
__device__ __forceinline__ uint32_t smem_u32(const void* p) {
    uint32_t a;
    asm("{ .reg .u64 t; cvta.to.shared.u64 t, %1; cvt.u32.u64 %0, t; }" : "=r"(a) : "l"(p));
    return a;
}
__device__ __forceinline__ void split_bf16(float v, bf16& h, bf16& l) {
    h = __float2bfloat16(v);
    l = __float2bfloat16(v - __bfloat162float(h));
}
__device__ __forceinline__ void ldsm4(uint32_t* r, uint32_t a) {
    asm volatile("ldmatrix.sync.aligned.m8n8.x4.shared.b16 {%0,%1,%2,%3}, [%4];"
        : "=r"(r[0]), "=r"(r[1]), "=r"(r[2]), "=r"(r[3]) : "r"(a));
}
__device__ __forceinline__ void mma16816(float* c, const uint32_t* a, const uint32_t* b) {
    asm volatile("mma.sync.aligned.m16n8k16.row.col.f32.bf16.bf16.f32 "
        "{%0,%1,%2,%3}, {%4,%5,%6,%7}, {%8,%9}, {%0,%1,%2,%3};"
        : "+f"(c[0]), "+f"(c[1]), "+f"(c[2]), "+f"(c[3])
        : "r"(a[0]), "r"(a[1]), "r"(a[2]), "r"(a[3]), "r"(b[0]), "r"(b[1]));
}

__device__ __forceinline__ float block_sum(float v) {
    __shared__ float sh[8]; __shared__ float tot;
    __syncthreads();
    int lane = threadIdx.x & 31, w = threadIdx.x >> 5;
    int nw = blockDim.x >> 5;
    #pragma unroll
    for (int o = 16; o; o >>= 1) v += __shfl_xor_sync(0xffffffffu, v, o);
    if (lane == 0) sh[w] = v;
    __syncthreads();
    if (w == 0) {
        float t = (lane < nw) ? sh[lane] : 0.f;
        #pragma unroll
        for (int o = 4; o; o >>= 1) t += __shfl_xor_sync(0xffffffffu, t, o);
        if (lane == 0) tot = t;
    }
    __syncthreads();
    return tot;
}
__device__ __forceinline__ float block_max(float v) {
    __shared__ float sh[8]; __shared__ float tot;
    __syncthreads();
    int lane = threadIdx.x & 31, w = threadIdx.x >> 5;
    int nw = blockDim.x >> 5;
    #pragma unroll
    for (int o = 16; o; o >>= 1) v = fmaxf(v, __shfl_xor_sync(0xffffffffu, v, o));
    if (lane == 0) sh[w] = v;
    __syncthreads();
    if (w == 0) {
        float t = (lane < nw) ? sh[lane] : -3.4e38f;
        #pragma unroll
        for (int o = 4; o; o >>= 1) t = fmaxf(t, __shfl_xor_sync(0xffffffffu, t, o));
        if (lane == 0) tot = t;
    }
    __syncthreads();
    return tot;
}

// ---------------- embedding + PE -------------------------------------------
__global__ __launch_bounds__(256) void embed_kernel(
    const int* __restrict__ ids, const float* __restrict__ emb,
    float* __restrict__ x, bf16* __restrict__ xh, bf16* __restrict__ xl)
{
    int row = blockIdx.x;
    int s   = row & (S_-1);
    int tok = ids[row];
    size_t base = (size_t)row * D_;
    const float NEG = -9.210340371976184f / (float)D_;
    #pragma unroll
    for (int i = 0; i < 3; i++) {
        int d = threadIdx.x + i*256;
        int k2 = (d >> 1) << 1;
        float ang = (float)s * __expf((float)k2 * NEG);
        float pe  = (d & 1) ? cosf(ang) : sinf(ang);
        float v = emb[(size_t)tok * D_ + d] + pe;
        x[base + d] = v;
        bf16 h, l; split_bf16(v, h, l);
        xh[base + d] = h; xl[base + d] = l;
    }
}

// ---------------- weight prep -----------------------------------------------
// QKVO: 4 weight arrays [L][K=768][N=768] -> out [l][m][N][K] hi/lo
__global__ __launch_bounds__(256) void wprep_qkvo(
    const float* __restrict__ W0, const float* __restrict__ W1,
    const float* __restrict__ W2, const float* __restrict__ W3,
    bf16* __restrict__ Th, bf16* __restrict__ Tl)
{
    __shared__ float t[32][33];
    int tx = threadIdx.x & 31, ty = threadIdx.x >> 5;
    int n0 = blockIdx.x * 32, k0 = blockIdx.y * 32;
    int z = blockIdx.z, l = z >> 2, m = z & 3;
    const float* W = (m == 0 ? W0 : m == 1 ? W1 : m == 2 ? W2 : W3)
                   + (size_t)l * D_ * D_;
    size_t obase = (size_t)z * D_ * D_;
    #pragma unroll
    for (int i = ty; i < 32; i += 8)
        t[i][tx] = W[(size_t)(k0 + i) * D_ + n0 + tx];
    __syncthreads();
    #pragma unroll
    for (int i = ty; i < 32; i += 8) {
        float v = t[tx][i];
        bf16 h, l2; split_bf16(v, h, l2);
        size_t o = obase + (size_t)(n0 + i) * D_ + k0 + tx;
        Th[o] = h; Tl[o] = l2;
    }
}

// generic: W [L][K][N] -> out [l][N][K] hi/lo, z = layer
__global__ __launch_bounds__(256) void wprep_l(
    const float* __restrict__ W, bf16* __restrict__ Th, bf16* __restrict__ Tl,
    int K, int N)
{
    __shared__ float t[32][33];
    int tx = threadIdx.x & 31, ty = threadIdx.x >> 5;
    int n0 = blockIdx.x * 32, k0 = blockIdx.y * 32;
    int l = blockIdx.z;
    const float* Wb = W + (size_t)l * K * N;
    size_t obase = (size_t)l * K * N;
    #pragma unroll
    for (int i = ty; i < 32; i += 8)
        t[i][tx] = Wb[(size_t)(k0 + i) * N + n0 + tx];
    __syncthreads();
    #pragma unroll
    for (int i = ty; i < 32; i += 8) {
        float v = t[tx][i];
        bf16 h, l2; split_bf16(v, h, l2);
        size_t o = obase + (size_t)(n0 + i) * K + k0 + tx;
        Th[o] = h; Tl[o] = l2;
    }
}

// ---------------- V transpose: v[rows,768] -> vt[bh][dk][s] -----------------
__global__ __launch_bounds__(256) void vtrans(
    const bf16* __restrict__ vh, const bf16* __restrict__ vl,
    bf16* __restrict__ vth, bf16* __restrict__ vtl)
{
    __shared__ bf16 th[32][33], tl[32][33];
    int tx = threadIdx.x & 31, ty = threadIdx.x >> 5;
    int s0 = blockIdx.x * 32, d0 = blockIdx.y * 32;
    int bh = blockIdx.z, b = bh / H_, h = bh % H_;
    #pragma unroll
    for (int i = ty; i < 32; i += 8) {
        size_t src = (size_t)(b*S_ + s0 + i) * D_ + h*DK_ + d0 + tx;
        th[i][tx] = vh[src]; tl[i][tx] = vl[src];
    }
    __syncthreads();
    #pragma unroll
    for (int i = ty; i < 32; i += 8) {
        size_t dst = (size_t)(bh*DK_ + d0 + i) * S_ + s0 + tx;
        vth[dst] = th[tx][i]; vtl[dst] = tl[tx][i];
    }
}

// ---------------- generic warp-MMA GEMM -------------------------------------
// modes: 0 fp32+bias | 1 split+bias | 2 relu+split+bias | 3 scores | 4 split noBias (col guard)
#define ROWB  80
#define TILEB (128*ROWB)
#define BUFB  (4*TILEB)
#define GSMEM (2*BUFB)        // 81920

__global__ __launch_bounds__(256) void gemm_mma(
    const bf16* __restrict__ Ah, const bf16* __restrict__ Al,
    unsigned long long aSB, unsigned long long aSH, int lda,
    const bf16* __restrict__ Bh, const bf16* __restrict__ Bl,
    unsigned long long bSB, unsigned long long bSH, int ldb,
    const float* __restrict__ bias, const float* __restrict__ relb,
    float* __restrict__ Cf, bf16* __restrict__ Ch, bf16* __restrict__ Cl,
    unsigned long long cSB, unsigned long long cSH, int ldo,
    int N, int K, int mode)
{
    extern __shared__ char sm[];
    uint32_t sb = smem_u32(sm);
    int tid = threadIdx.x, lane = tid & 31, wid = tid >> 5;
    int bx = blockIdx.x, by = blockIdx.y, bz = blockIdx.z;
    int b_ = bz / H_, h_ = bz % H_;
    const bf16* pAh = Ah + (size_t)b_*aSB + (size_t)h_*aSH;
    const bf16* pAl = Al + (size_t)b_*aSB + (size_t)h_*aSH;
    const bf16* pBh = Bh + (size_t)b_*bSB + (size_t)h_*bSH;
    const bf16* pBl = Bl + (size_t)b_*bSB + (size_t)h_*bSH;
    int wm = wid & 3, wn = wid >> 2;
    bool act = (bx*128 + wn*64) < N;     // warp-level column activity (PV N=64)

    float acc[2][8][4];
    #pragma unroll
    for (int i = 0; i < 2; i++)
        #pragma unroll
        for (int j = 0; j < 8; j++)
            #pragma unroll
            for (int q = 0; q < 4; q++) acc[i][j][q] = 0.f;

    uint32_t aoffs = (uint32_t)((wm*32 + (lane & 15))*ROWB) + (((uint32_t)lane >> 4) << 4);
    uint32_t boffs = (uint32_t)((wn*64 + (lane & 7) + ((lane >> 4) << 3))*ROWB)
                   + ((((uint32_t)lane >> 3) & 1) << 4);

    int nch = K >> 5;

    auto load_chunk = [&](int kt, int bufi) {
        int k0 = kt << 5;
        uint32_t dbase = sb + bufi*BUFB;
        #pragma unroll
        for (int i = 0; i < 8; i++) {
            int idx = tid + (i << 8);
            int tile = idx >> 9;
            int r = (idx >> 2) & 127;
            int c = idx & 3;
            uint32_t dst = dbase + tile*TILEB + r*ROWB + (c << 4);
            if (tile == 0) {
                const bf16* s = pAh + (size_t)(by*128 + r)*lda + k0 + c*8;
                asm volatile("cp.async.cg.shared.global [%0], [%1], 16;" :: "r"(dst), "l"(s));
            } else if (tile == 1) {
                const bf16* s = pAl + (size_t)(by*128 + r)*lda + k0 + c*8;
                asm volatile("cp.async.cg.shared.global [%0], [%1], 16;" :: "r"(dst), "l"(s));
            } else {
                int n = bx*128 + r;
                int nc = n < N ? n : 0;
                const bf16* s = (tile == 2 ? pBh : pBl) + (size_t)nc*ldb + k0 + c*8;
                uint32_t sz = (n < N) ? 16u : 0u;
                asm volatile("cp.async.cg.shared.global [%0], [%1], 16, %2;"
                             :: "r"(dst), "l"(s), "r"(sz));
            }
        }
        asm volatile("cp.async.commit_group;" ::: "memory");
    };

    load_chunk(0, 0);
    for (int kt = 0; kt < nch; kt++) {
        int bufi = kt & 1;
        if (kt + 1 < nch) {
            load_chunk(kt + 1, bufi ^ 1);
            asm volatile("cp.async.wait_group 1;" ::: "memory");
        } else {
            asm volatile("cp.async.wait_group 0;" ::: "memory");
        }
        __syncthreads();
        if (act) {
            uint32_t base = sb + bufi*BUFB;
            #pragma unroll
            for (int ks = 0; ks < 2; ks++) {
                uint32_t kb = (uint32_t)ks << 5;
                uint32_t aH[2][4], aL[2][4], bH[4][4], bL[4][4];
                #pragma unroll
                for (int mt = 0; mt < 2; mt++)
                    ldsm4(aH[mt], base + aoffs + mt*(16*ROWB) + kb);
                #pragma unroll
                for (int p = 0; p < 4; p++)
                    ldsm4(bH[p], base + 2*TILEB + boffs + p*(16*ROWB) + kb);
                #pragma unroll
                for (int mt = 0; mt < 2; mt++)
                    #pragma unroll
                    for (int nt = 0; nt < 8; nt++)
                        mma16816(acc[mt][nt], aH[mt], &bH[nt >> 1][(nt & 1) << 1]);
                #pragma unroll
                for (int p = 0; p < 4; p++)
                    ldsm4(bL[p], base + 3*TILEB + boffs + p*(16*ROWB) + kb);
                #pragma unroll
                for (int mt = 0; mt < 2; mt++)
                    #pragma unroll
                    for (int nt = 0; nt < 8; nt++)
                        mma16816(acc[mt][nt], aH[mt], &bL[nt >> 1][(nt & 1) << 1]);
                #pragma unroll
                for (int mt = 0; mt < 2; mt++)
                    ldsm4(aL[mt], base + TILEB + aoffs + mt*(16*ROWB) + kb);
                #pragma unroll
                for (int mt = 0; mt < 2; mt++)
                    #pragma unroll
                    for (int nt = 0; nt < 8; nt++)
                        mma16816(acc[mt][nt], aL[mt], &bH[nt >> 1][(nt & 1) << 1]);
            }
        }
        __syncthreads();
    }

    // ---------------- epilogue ----------------
    if (!act) return;
    size_t cOff = (size_t)b_*cSB + (size_t)h_*cSH;
    #pragma unroll
    for (int mt = 0; mt < 2; mt++) {
        #pragma unroll
        for (int nt = 0; nt < 8; nt++) {
            int rr = by*128 + wm*32 + mt*16 + (lane >> 2);
            int cc = bx*128 + wn*64 + nt*8 + ((lane & 3) << 1);
            #pragma unroll
            for (int hf = 0; hf < 2; hf++) {
                int r = rr + hf*8;
                float v0 = acc[mt][nt][hf*2], v1 = acc[mt][nt][hf*2 + 1];
                size_t o = cOff + (size_t)r*ldo + cc;
                if (mode == 0) {
                    *(float2*)(Cf + o) = make_float2(v0 + bias[cc], v1 + bias[cc + 1]);
                } else if (mode == 3) {
                    float b0 = relb[(size_t)(cc - r + (S_-1))*H_ + h_];
                    float b1 = relb[(size_t)(cc + 1 - r + (S_-1))*H_ + h_];
                    *(float2*)(Cf + o) = make_float2(fmaf(v0, 0.125f, b0),
                                                     fmaf(v1, 0.125f, b1));
                } else {
                    if (mode == 4) { if (cc >= N) continue; }
                    else { v0 += bias[cc]; v1 += bias[cc + 1]; }
                    if (mode == 2) { v0 = fmaxf(v0, 0.f); v1 = fmaxf(v1, 0.f); }
                    bf16 h0, l0, h1, l1;
                    split_bf16(v0, h0, l0); split_bf16(v1, h1, l1);
                    __nv_bfloat162 hv; hv.x = h0; hv.y = h1;
                    __nv_bfloat162 lv; lv.x = l0; lv.y = l1;
                    *(__nv_bfloat162*)(Ch + o) = hv;
                    *(__nv_bfloat162*)(Cl + o) = lv;
                }
            }
        }
    }
}

// ---------------- softmax (fp32 in, bf16 hi/lo out), 128 thr/row ------------
__global__ __launch_bounds__(128) void softmax512(
    const float* __restrict__ sc, bf16* __restrict__ ph, bf16* __restrict__ pl)
{
    size_t base = (size_t)blockIdx.x * S_;
    int tid = threadIdx.x;
    float4 v = *(const float4*)(sc + base + tid*4);
    float M = block_max(fmaxf(fmaxf(v.x, v.y), fmaxf(v.z, v.w)));
    float e0 = __expf(v.x - M), e1 = __expf(v.y - M);
    float e2 = __expf(v.z - M), e3 = __expf(v.w - M);
    float inv = 1.f / block_sum(e0 + e1 + e2 + e3);
    float p[4] = {e0*inv, e1*inv, e2*inv, e3*inv};
    uint32_t hp[2], lp[2];
    #pragma unroll
    for (int i = 0; i < 2; i++) {
        bf16 h0, l0, h1, l1;
        split_bf16(p[i*2], h0, l0); split_bf16(p[i*2+1], h1, l1);
        __nv_bfloat162 hv; hv.x = h0; hv.y = h1;
        __nv_bfloat162 lv; lv.x = l0; lv.y = l1;
        hp[i] = *(uint32_t*)&hv; lp[i] = *(uint32_t*)&lv;
    }
    *(uint2*)(ph + base + tid*4) = make_uint2(hp[0], hp[1]);
    *(uint2*)(pl + base + tid*4) = make_uint2(lp[0], lp[1]);
}

// ---------------- x = LayerNorm(x + t); writes fp32 + hi/lo -----------------
__global__ __launch_bounds__(256) void add_ln(
    float* __restrict__ x, const float* __restrict__ t,
    const float* __restrict__ g, const float* __restrict__ bb,
    bf16* __restrict__ xh, bf16* __restrict__ xl)
{
    int row = blockIdx.x, tid = threadIdx.x;
    size_t base = (size_t)row * D_;
    float v[4]; float s = 0.f;
    bool on = tid < 192;
    if (on) {
        float4 a = *(const float4*)(x + base + tid*4);
        float4 c = *(const float4*)(t + base + tid*4);
        v[0] = a.x + c.x; v[1] = a.y + c.y; v[2] = a.z + c.z; v[3] = a.w + c.w;
        s = v[0] + v[1] + v[2] + v[3];
    } else { v[0] = v[1] = v[2] = v[3] = 0.f; }
    float mean = block_sum(s) * (1.f/(float)D_);
    float ss = 0.f;
    if (on) {
        #pragma unroll
        for (int i = 0; i < 4; i++) { float d = v[i]-mean; ss += d*d; }
    }
    float rstd = rsqrtf(block_sum(ss) * (1.f/(float)D_) + 1e-5f);
    if (on) {
        float4 gg = *(const float4*)(g + tid*4);
        float4 bv = *(const float4*)(bb + tid*4);
        float o0 = (v[0]-mean)*rstd*gg.x + bv.x;
        float o1 = (v[1]-mean)*rstd*gg.y + bv.y;
        float o2 = (v[2]-mean)*rstd*gg.z + bv.z;
        float o3 = (v[3]-mean)*rstd*gg.w + bv.w;
        *(float4*)(x + base + tid*4) = make_float4(o0, o1, o2, o3);
        bf16 h0,l0,h1,l1,h2,l2,h3,l3;
        split_bf16(o0,h0,l0); split_bf16(o1,h1,l1);
        split_bf16(o2,h2,l2); split_bf16(o3,h3,l3);
        __nv_bfloat162 ha; ha.x=h0; ha.y=h1;
        __nv_bfloat162 hbv; hbv.x=h2; hbv.y=h3;
        __nv_bfloat162 la; la.x=l0; la.y=l1;
        __nv_bfloat162 lb; lb.x=l2; lb.y=l3;
        *(uint2*)(xh + base + tid*4) = make_uint2(*(uint32_t*)&ha, *(uint32_t*)&hbv);
        *(uint2*)(xl + base + tid*4) = make_uint2(*(uint32_t*)&la, *(uint32_t*)&lb);
    }
}

// ---------------- head ------------------------------------------------------
__global__ __launch_bounds__(256) void meanpool(
    const float* __restrict__ x, float* __restrict__ pool)
{
    int d = blockIdx.x*256 + threadIdx.x;
    int b = blockIdx.y;
    float s = 0.f;
    for (int t = 0; t < S_; t++) s += x[((size_t)b*S_ + t)*D_ + d];
    pool[b*D_ + d] = s * (1.f/(float)S_);
}
__global__ __launch_bounds__(256) void fc1(
    const float* __restrict__ pool, const float* __restrict__ w,
    const float* __restrict__ bias, float* __restrict__ out)
{
    int idx = blockIdx.x*256 + threadIdx.x;
    int b = idx / (D_/2), j = idx % (D_/2);
    float s = bias[j];
    for (int d = 0; d < D_; d++) s = fmaf(pool[b*D_ + d], w[d*(D_/2) + j], s);
    out[idx] = fmaxf(s, 0.f);
}
__global__ __launch_bounds__(256) void fc2(
    const float* __restrict__ h, const float* __restrict__ w,
    const float* __restrict__ bias, float* __restrict__ out)
{
    int idx = blockIdx.x*256 + threadIdx.x;
    if (idx >= B_*NC_) return;
    int b = idx / NC_, c = idx % NC_;
    float s = bias[c];
    for (int j = 0; j < D_/2; j++) s = fmaf(h[b*(D_/2) + j], w[j*NC_ + c], s);
    out[idx] = s;
}

// ---------------- launch ----------------------------------------------------
extern "C" void kernel_launch(void* const* d_in, const int* in_sizes, int n_in,
                              void* d_out, int out_size)
{
    const int*   ids  = (const int*)  d_in[0];
    const float* emb  = (const float*)d_in[1];
    const float* wq   = (const float*)d_in[2];
    const float* bq   = (const float*)d_in[3];
    const float* wk   = (const float*)d_in[4];
    const float* bk   = (const float*)d_in[5];
    const float* wv   = (const float*)d_in[6];
    const float* bv   = (const float*)d_in[7];
    const float* wo   = (const float*)d_in[8];
    const float* bo   = (const float*)d_in[9];
    const float* relb = (const float*)d_in[10];
    const float* w1   = (const float*)d_in[11];
    const float* b1   = (const float*)d_in[12];
    const float* w2   = (const float*)d_in[13];
    const float* b2   = (const float*)d_in[14];
    const float* l1g  = (const float*)d_in[15];
    const float* l1b  = (const float*)d_in[16];
    const float* l2g  = (const float*)d_in[17];
    const float* l2b  = (const float*)d_in[18];
    const float* cw1  = (const float*)d_in[19];
    const float* cb1  = (const float*)d_in[20];
    const float* cw2  = (const float*)d_in[21];
    const float* cb2  = (const float*)d_in[22];

    cudaFuncSetAttribute(gemm_mma, cudaFuncAttributeMaxDynamicSharedMemorySize, GSMEM);

    float *x, *t, *sc, *pool, *chd;
    bf16 *xh,*xl,*qh,*ql,*kh,*kl,*vh,*vl,*vth,*vtl,*cxh,*cxl,*fh,*fl,*ph,*pl;
    bf16 *wqkh,*wqkl,*w1h,*w1l,*w2h,*w2l;
    cudaGetSymbolAddress((void**)&x,   g_x);
    cudaGetSymbolAddress((void**)&t,   g_t);
    cudaGetSymbolAddress((void**)&sc,  g_sc);
    cudaGetSymbolAddress((void**)&pool,g_pool);
    cudaGetSymbolAddress((void**)&chd, g_chd);
    cudaGetSymbolAddress((void**)&xh,  g_xh);
    cudaGetSymbolAddress((void**)&xl,  g_xl);
    cudaGetSymbolAddress((void**)&qh,  g_qh);
    cudaGetSymbolAddress((void**)&ql,  g_ql);
    cudaGetSymbolAddress((void**)&kh,  g_kh);
    cudaGetSymbolAddress((void**)&kl,  g_kl);
    cudaGetSymbolAddress((void**)&vh,  g_vh);
    cudaGetSymbolAddress((void**)&vl,  g_vl);
    cudaGetSymbolAddress((void**)&vth, g_vth);
    cudaGetSymbolAddress((void**)&vtl, g_vtl);
    cudaGetSymbolAddress((void**)&cxh, g_cxh);
    cudaGetSymbolAddress((void**)&cxl, g_cxl);
    cudaGetSymbolAddress((void**)&fh,  g_fh);
    cudaGetSymbolAddress((void**)&fl,  g_fl);
    cudaGetSymbolAddress((void**)&ph,  g_ph);
    cudaGetSymbolAddress((void**)&pl,  g_pl);
    cudaGetSymbolAddress((void**)&wqkh,g_wqkh);
    cudaGetSymbolAddress((void**)&wqkl,g_wqkl);
    cudaGetSymbolAddress((void**)&w1h, g_w1h);
    cudaGetSymbolAddress((void**)&w1l, g_w1l);
    cudaGetSymbolAddress((void**)&w2h, g_w2h);
    cudaGetSymbolAddress((void**)&w2l, g_w2l);

    // launch 0: embed; 1-3: all weight prep (so launch #5 = full-size gemm)
    embed_kernel<<<ROWS, 256>>>(ids, emb, x, xh, xl);
    wprep_qkvo<<<dim3(D_/32, D_/32, L_*4), 256>>>(wq, wk, wv, wo, wqkh, wqkl);
    wprep_l<<<dim3(DFF_/32, D_/32, L_), 256>>>(w1, w1h, w1l, D_, DFF_);
    wprep_l<<<dim3(D_/32, DFF_/32, L_), 256>>>(w2, w2h, w2l, DFF_, D_);

    dim3 gDD(D_/128, ROWS/128, 1);
    dim3 gF1(DFF_/128, ROWS/128, 1);
    dim3 gSC(S_/128, S_/128, BH_);
    dim3 gPV(1, S_/128, BH_);

    for (int l = 0; l < L_; l++) {
        const bf16* Wqh = wqkh + ((size_t)l*4 + 0)*D_*D_;
        const bf16* Wql = wqkl + ((size_t)l*4 + 0)*D_*D_;
        const bf16* Wkh = wqkh + ((size_t)l*4 + 1)*D_*D_;
        const bf16* Wkl = wqkl + ((size_t)l*4 + 1)*D_*D_;
        const bf16* Wvh = wqkh + ((size_t)l*4 + 2)*D_*D_;
        const bf16* Wvl = wqkl + ((size_t)l*4 + 2)*D_*D_;
        const bf16* Woh = wqkh + ((size_t)l*4 + 3)*D_*D_;
        const bf16* Wol = wqkl + ((size_t)l*4 + 3)*D_*D_;
        const bf16* W1h = w1h + (size_t)l*D_*DFF_;
        const bf16* W1l = w1l + (size_t)l*D_*DFF_;
        const bf16* W2h = w2h + (size_t)l*DFF_*D_;
        const bf16* W2l = w2l + (size_t)l*DFF_*D_;
        const float* Rb = relb + (size_t)l*(2*S_-1)*H_;

        gemm_mma<<<gDD, 256, GSMEM>>>(xh, xl, 0, 0, D_, Wqh, Wql, 0, 0, D_,
            bq + l*D_, nullptr, nullptr, qh, ql, 0, 0, D_, D_, D_, 1);
        gemm_mma<<<gDD, 256, GSMEM>>>(xh, xl, 0, 0, D_, Wkh, Wkl, 0, 0, D_,
            bk + l*D_, nullptr, nullptr, kh, kl, 0, 0, D_, D_, D_, 1);
        gemm_mma<<<gDD, 256, GSMEM>>>(xh, xl, 0, 0, D_, Wvh, Wvl, 0, 0, D_,
            bv + l*D_, nullptr, nullptr, vh, vl, 0, 0, D_, D_, D_, 1);
        vtrans<<<dim3(S_/32, DK_/32, BH_), 256>>>(vh, vl, vth, vtl);

        gemm_mma<<<gSC, 256, GSMEM>>>(
            qh, ql, (unsigned long long)S_*D_, DK_, D_,
            kh, kl, (unsigned long long)S_*D_, DK_, D_,
            nullptr, Rb,
            sc, nullptr, nullptr,
            (unsigned long long)H_*S_*S_, (unsigned long long)S_*S_, S_,
            S_, DK_, 3);
        softmax512<<<BH_*S_, 128>>>(sc, ph, pl);
        gemm_mma<<<gPV, 256, GSMEM>>>(
            ph, pl, (unsigned long long)H_*S_*S_, (unsigned long long)S_*S_, S_,
            vth, vtl, (unsigned long long)H_*DK_*S_, (unsigned long long)DK_*S_, S_,
            nullptr, nullptr,
            nullptr, cxh, cxl,
            (unsigned long long)S_*D_, DK_, D_,
            DK_, S_, 4);

        gemm_mma<<<gDD, 256, GSMEM>>>(cxh, cxl, 0, 0, D_, Woh, Wol, 0, 0, D_,
            bo + l*D_, nullptr, t, nullptr, nullptr, 0, 0, D_, D_, D_, 0);
        add_ln<<<ROWS, 256>>>(x, t, l1g + l*D_, l1b + l*D_, xh, xl);

        gemm_mma<<<gF1, 256, GSMEM>>>(xh, xl, 0, 0, D_, W1h, W1l, 0, 0, D_,
            b1 + l*DFF_, nullptr, nullptr, fh, fl, 0, 0, DFF_, DFF_, D_, 2);
        gemm_mma<<<gDD, 256, GSMEM>>>(fh, fl, 0, 0, DFF_, W2h, W2l, 0, 0, DFF_,
            b2 + l*D_, nullptr, t, nullptr, nullptr, 0, 0, D_, D_, DFF_, 0);
        add_ln<<<ROWS, 256>>>(x, t, l2g + l*D_, l2b + l*D_, xh, xl);
    }

    meanpool<<<dim3(D_/256, B_), 256>>>(x, pool);
    fc1<<<(B_*(D_/2))/256, 256>>>(pool, cw1, cb1, chd);
    fc2<<<(B_*NC_ + 255)/256, 256>>>(chd, cw2, cb2, (float*)d_out);
}

// round 6
// speedup vs baseline: 2.8199x; 1.3236x over previous
#include <cuda_runtime.h>
#include <cuda_bf16.h>
#include <cstdint>
#include <cstddef>

#define D_    768
#define H_    12
#define DK_   64
#define DFF_  3072
#define L_    12
#define NC_   100
#define S_    512
#define B_    16
#define ROWS  (B_*S_)          // 8192
#define BH_   (B_*H_)          // 192
#define QKVN  2304

typedef __nv_bfloat16 bf16;

// ---------------- scratch (static device globals; no allocation) ----------
__device__ __align__(256) float g_x   [ROWS*(size_t)D_];
__device__ __align__(256) float g_t   [ROWS*(size_t)D_];
__device__ __align__(256) bf16  g_xh  [ROWS*(size_t)D_];
__device__ __align__(256) bf16  g_xl  [ROWS*(size_t)D_];
__device__ __align__(256) bf16  g_qkvh[ROWS*(size_t)QKVN];
__device__ __align__(256) bf16  g_qkvl[ROWS*(size_t)QKVN];
__device__ __align__(256) bf16  g_cxh [ROWS*(size_t)D_];
__device__ __align__(256) bf16  g_cxl [ROWS*(size_t)D_];
__device__ __align__(256) bf16  g_fh  [ROWS*(size_t)DFF_];
__device__ __align__(256) bf16  g_fl  [ROWS*(size_t)DFF_];
// pre-split transposed weights for ALL layers
__device__ __align__(256) bf16  g_wqkvh[(size_t)L_*QKVN*D_]; // [l][N=2304][K=768]
__device__ __align__(256) bf16  g_wqkvl[(size_t)L_*QKVN*D_];
__device__ __align__(256) bf16  g_woh [(size_t)L_*D_*D_];
__device__ __align__(256) bf16  g_wol [(size_t)L_*D_*D_];
__device__ __align__(256) bf16  g_w1h [(size_t)L_*DFF_*D_];
__device__ __align__(256) bf16  g_w1l [(size_t)L_*DFF_*D_];
__device__ __align__(256) bf16  g_w2h [(size_t)L_*DFF_*D_];
__device__ __align__(256) bf16  g_w2l [(size_t)L_*DFF_*D_];
__device__ __align__(256) float g_bqkv[(size_t)L_*QKVN];
__device__ __align__(256) float g_pool[B_*D_];
__device__ __align__(256) float g_chd [B_*(D_/2)];

// ---------------- helpers ---------------------------------------------------
__device__ __forceinline__ uint32_t smem_u32(const void* p) {
    uint32_t a;
    asm("{ .reg .u64 t; cvta.to.shared.u64 t, %1; cvt.u32.u64 %0, t; }" : "=r"(a) : "l"(p));
    return a;
}
__device__ __forceinline__ void split_bf16(float v, bf16& h, bf16& l) {
    h = __float2bfloat16(v);
    l = __float2bfloat16(v - __bfloat162float(h));
}
__device__ __forceinline__ void split2(float a, float b, uint32_t& hp, uint32_t& lp) {
    bf16 h0, l0, h1, l1;
    split_bf16(a, h0, l0); split_bf16(b, h1, l1);
    __nv_bfloat162 hv; hv.x = h0; hv.y = h1;
    __nv_bfloat162 lv; lv.x = l0; lv.y = l1;
    hp = *(uint32_t*)&hv; lp = *(uint32_t*)&lv;
}
__device__ __forceinline__ void ldsm4(uint32_t* r, uint32_t a) {
    asm volatile("ldmatrix.sync.aligned.m8n8.x4.shared.b16 {%0,%1,%2,%3}, [%4];"
        : "=r"(r[0]), "=r"(r[1]), "=r"(r[2]), "=r"(r[3]) : "r"(a));
}
__device__ __forceinline__ void ldsm4t(uint32_t* r, uint32_t a) {
    asm volatile("ldmatrix.sync.aligned.m8n8.x4.trans.shared.b16 {%0,%1,%2,%3}, [%4];"
        : "=r"(r[0]), "=r"(r[1]), "=r"(r[2]), "=r"(r[3]) : "r"(a));
}
__device__ __forceinline__ void mma16816(float* c, const uint32_t* a, const uint32_t* b) {
    asm volatile("mma.sync.aligned.m16n8k16.row.col.f32.bf16.bf16.f32 "
        "{%0,%1,%2,%3}, {%4,%5,%6,%7}, {%8,%9}, {%0,%1,%2,%3};"
        : "+f"(c[0]), "+f"(c[1]), "+f"(c[2]), "+f"(c[3])
        : "r"(a[0]), "r"(a[1]), "r"(a[2]), "r"(a[3]), "r"(b[0]), "r"(b[1]));
}
__device__ __forceinline__ void cpasync16(uint32_t dst, const void* src) {
    asm volatile("cp.async.cg.shared.global [%0], [%1], 16;" :: "r"(dst), "l"(src));
}

__device__ __forceinline__ float block_sum(float v) {
    __shared__ float sh[8]; __shared__ float tot;
    __syncthreads();
    int lane = threadIdx.x & 31, w = threadIdx.x >> 5;
    int nw = blockDim.x >> 5;
    #pragma unroll
    for (int o = 16; o; o >>= 1) v += __shfl_xor_sync(0xffffffffu, v, o);
    if (lane == 0) sh[w] = v;
    __syncthreads();
    if (w == 0) {
        float t = (lane < nw) ? sh[lane] : 0.f;
        #pragma unroll
        for (int o = 4; o; o >>= 1) t += __shfl_xor_sync(0xffffffffu, t, o);
        if (lane == 0) tot = t;
    }
    __syncthreads();
    return tot;
}

// ---------------- embedding + PE -------------------------------------------
__global__ __launch_bounds__(256) void embed_kernel(
    const int* __restrict__ ids, const float* __restrict__ emb,
    float* __restrict__ x, bf16* __restrict__ xh, bf16* __restrict__ xl)
{
    int row = blockIdx.x;
    int s   = row & (S_-1);
    int tok = ids[row];
    size_t base = (size_t)row * D_;
    const float NEG = -9.210340371976184f / (float)D_;
    #pragma unroll
    for (int i = 0; i < 3; i++) {
        int d = threadIdx.x + i*256;
        int k2 = (d >> 1) << 1;
        float ang = (float)s * __expf((float)k2 * NEG);
        float pe  = (d & 1) ? cosf(ang) : sinf(ang);
        float v = emb[(size_t)tok * D_ + d] + pe;
        x[base + d] = v;
        bf16 h, l; split_bf16(v, h, l);
        xh[base + d] = h; xl[base + d] = l;
    }
}

// ---------------- weight prep -----------------------------------------------
// pack Q,K,V weights: [L][K=768][N=768] x3 -> [l][N=2304][K=768] hi/lo
__global__ __launch_bounds__(256) void wprep_qkv3(
    const float* __restrict__ Wq, const float* __restrict__ Wk,
    const float* __restrict__ Wv,
    bf16* __restrict__ Th, bf16* __restrict__ Tl)
{
    __shared__ float t[32][33];
    int tx = threadIdx.x & 31, ty = threadIdx.x >> 5;
    int n0 = blockIdx.x * 32, k0 = blockIdx.y * 32;
    int z = blockIdx.z, l = z / 3, m = z % 3;
    const float* W = (m == 0 ? Wq : m == 1 ? Wk : Wv) + (size_t)l * D_ * D_;
    size_t obase = (size_t)z * D_ * D_;   // = l*2304*768 + m*768*768
    #pragma unroll
    for (int i = ty; i < 32; i += 8)
        t[i][tx] = W[(size_t)(k0 + i) * D_ + n0 + tx];
    __syncthreads();
    #pragma unroll
    for (int i = ty; i < 32; i += 8) {
        float v = t[tx][i];
        bf16 h, l2; split_bf16(v, h, l2);
        size_t o = obase + (size_t)(n0 + i) * D_ + k0 + tx;
        Th[o] = h; Tl[o] = l2;
    }
}

// generic: W [L][K][N] -> out [l][N][K] hi/lo, z = layer
__global__ __launch_bounds__(256) void wprep_l(
    const float* __restrict__ W, bf16* __restrict__ Th, bf16* __restrict__ Tl,
    int K, int N)
{
    __shared__ float t[32][33];
    int tx = threadIdx.x & 31, ty = threadIdx.x >> 5;
    int n0 = blockIdx.x * 32, k0 = blockIdx.y * 32;
    int l = blockIdx.z;
    const float* Wb = W + (size_t)l * K * N;
    size_t obase = (size_t)l * K * N;
    #pragma unroll
    for (int i = ty; i < 32; i += 8)
        t[i][tx] = Wb[(size_t)(k0 + i) * N + n0 + tx];
    __syncthreads();
    #pragma unroll
    for (int i = ty; i < 32; i += 8) {
        float v = t[tx][i];
        bf16 h, l2; split_bf16(v, h, l2);
        size_t o = obase + (size_t)(n0 + i) * K + k0 + tx;
        Th[o] = h; Tl[o] = l2;
    }
}

__global__ __launch_bounds__(256) void bias_pack(
    const float* __restrict__ bq, const float* __restrict__ bk,
    const float* __restrict__ bv, float* __restrict__ out)
{
    int idx = blockIdx.x*256 + threadIdx.x;
    if (idx >= L_*QKVN) return;
    int l = idx / QKVN, j = idx % QKVN;
    float v = (j < 768) ? bq[l*768 + j]
            : (j < 1536) ? bk[l*768 + j - 768]
                         : bv[l*768 + j - 1536];
    out[idx] = v;
}

// ---------------- generic warp-MMA GEMM -------------------------------------
// modes: 0 fp32+bias | 1 split+bias | 2 relu+split+bias
#define ROWB  80
#define TILEB (128*ROWB)
#define BUFB  (4*TILEB)
#define GSMEM (2*BUFB)        // 81920

__global__ __launch_bounds__(256) void gemm_mma(
    const bf16* __restrict__ Ah, const bf16* __restrict__ Al, int lda,
    const bf16* __restrict__ Bh, const bf16* __restrict__ Bl, int ldb,
    const float* __restrict__ bias,
    float* __restrict__ Cf, bf16* __restrict__ Ch, bf16* __restrict__ Cl,
    int ldo, int N, int K, int mode)
{
    extern __shared__ char sm[];
    uint32_t sb = smem_u32(sm);
    int tid = threadIdx.x, lane = tid & 31, wid = tid >> 5;
    int bx = blockIdx.x, by = blockIdx.y;
    int wm = wid & 3, wn = wid >> 2;

    float acc[2][8][4];
    #pragma unroll
    for (int i = 0; i < 2; i++)
        #pragma unroll
        for (int j = 0; j < 8; j++)
            #pragma unroll
            for (int q = 0; q < 4; q++) acc[i][j][q] = 0.f;

    uint32_t aoffs = (uint32_t)((wm*32 + (lane & 15))*ROWB) + (((uint32_t)lane >> 4) << 4);
    uint32_t boffs = (uint32_t)((wn*64 + (lane & 7) + ((lane >> 4) << 3))*ROWB)
                   + ((((uint32_t)lane >> 3) & 1) << 4);

    int nch = K >> 5;

    auto load_chunk = [&](int kt, int bufi) {
        int k0 = kt << 5;
        uint32_t dbase = sb + bufi*BUFB;
        #pragma unroll
        for (int i = 0; i < 8; i++) {
            int idx = tid + (i << 8);
            int tile = idx >> 9;
            int r = (idx >> 2) & 127;
            int c = idx & 3;
            uint32_t dst = dbase + tile*TILEB + r*ROWB + (c << 4);
            const bf16* s;
            if (tile == 0)      s = Ah + (size_t)(by*128 + r)*lda + k0 + c*8;
            else if (tile == 1) s = Al + (size_t)(by*128 + r)*lda + k0 + c*8;
            else if (tile == 2) s = Bh + (size_t)(bx*128 + r)*ldb + k0 + c*8;
            else                s = Bl + (size_t)(bx*128 + r)*ldb + k0 + c*8;
            cpasync16(dst, s);
        }
        asm volatile("cp.async.commit_group;" ::: "memory");
    };

    load_chunk(0, 0);
    for (int kt = 0; kt < nch; kt++) {
        int bufi = kt & 1;
        if (kt + 1 < nch) {
            load_chunk(kt + 1, bufi ^ 1);
            asm volatile("cp.async.wait_group 1;" ::: "memory");
        } else {
            asm volatile("cp.async.wait_group 0;" ::: "memory");
        }
        __syncthreads();
        uint32_t base = sb + bufi*BUFB;
        #pragma unroll
        for (int ks = 0; ks < 2; ks++) {
            uint32_t kb = (uint32_t)ks << 5;
            uint32_t aH[2][4], aL[2][4], bH[4][4], bL[4][4];
            #pragma unroll
            for (int mt = 0; mt < 2; mt++)
                ldsm4(aH[mt], base + aoffs + mt*(16*ROWB) + kb);
            #pragma unroll
            for (int p = 0; p < 4; p++)
                ldsm4(bH[p], base + 2*TILEB + boffs + p*(16*ROWB) + kb);
            #pragma unroll
            for (int mt = 0; mt < 2; mt++)
                #pragma unroll
                for (int nt = 0; nt < 8; nt++)
                    mma16816(acc[mt][nt], aH[mt], &bH[nt >> 1][(nt & 1) << 1]);
            #pragma unroll
            for (int p = 0; p < 4; p++)
                ldsm4(bL[p], base + 3*TILEB + boffs + p*(16*ROWB) + kb);
            #pragma unroll
            for (int mt = 0; mt < 2; mt++)
                #pragma unroll
                for (int nt = 0; nt < 8; nt++)
                    mma16816(acc[mt][nt], aH[mt], &bL[nt >> 1][(nt & 1) << 1]);
            #pragma unroll
            for (int mt = 0; mt < 2; mt++)
                ldsm4(aL[mt], base + TILEB + aoffs + mt*(16*ROWB) + kb);
            #pragma unroll
            for (int mt = 0; mt < 2; mt++)
                #pragma unroll
                for (int nt = 0; nt < 8; nt++)
                    mma16816(acc[mt][nt], aL[mt], &bH[nt >> 1][(nt & 1) << 1]);
        }
        __syncthreads();
    }

    #pragma unroll
    for (int mt = 0; mt < 2; mt++) {
        #pragma unroll
        for (int nt = 0; nt < 8; nt++) {
            int rr = by*128 + wm*32 + mt*16 + (lane >> 2);
            int cc = bx*128 + wn*64 + nt*8 + ((lane & 3) << 1);
            #pragma unroll
            for (int hf = 0; hf < 2; hf++) {
                int r = rr + hf*8;
                float v0 = acc[mt][nt][hf*2] + bias[cc];
                float v1 = acc[mt][nt][hf*2 + 1] + bias[cc + 1];
                size_t o = (size_t)r*ldo + cc;
                if (mode == 0) {
                    *(float2*)(Cf + o) = make_float2(v0, v1);
                } else {
                    if (mode == 2) { v0 = fmaxf(v0, 0.f); v1 = fmaxf(v1, 0.f); }
                    uint32_t hp, lp; split2(v0, v1, hp, lp);
                    *(uint32_t*)(Ch + o) = hp;
                    *(uint32_t*)(Cl + o) = lp;
                }
            }
        }
    }
}

// ---------------- fused flash attention -------------------------------------
// CTA: 128 q-rows of one (b,h); loop 4 key-tiles of 128.
// S = QK^T/8 + relbias (3-pass hi/lo mma); online softmax; ctx += P V (3-pass).
#define FTS   18432              // 128 rows * 144B
#define FSMEM (10*FTS + 1024)    // Qh,Ql + 2 stages * (Kh,Kl,Vh,Vl) + bias tbl

__global__ __launch_bounds__(256) void flash_attn(
    const bf16* __restrict__ qkvh, const bf16* __restrict__ qkvl,
    const float* __restrict__ relb,
    bf16* __restrict__ cxh, bf16* __restrict__ cxl)
{
    extern __shared__ char sm[];
    uint32_t sb = smem_u32(sm);
    float* sbias = (float*)(sm + 10*FTS);
    int tid = threadIdx.x, lane = tid & 31, wid = tid >> 5;
    int q0 = blockIdx.x * 128;
    int bh = blockIdx.y, b = bh / H_, h = bh % H_;
    size_t rowbase = (size_t)b * S_;
    int hoff = h * DK_;

    // Q tile hi/lo
    for (int i = tid; i < 128*8; i += 256) {
        int r = i >> 3, c = i & 7;
        size_t g = (rowbase + q0 + r) * QKVN + hoff + c*8;
        uint32_t dst = sb + r*144 + c*16;
        cpasync16(dst, qkvh + g);
        cpasync16(dst + FTS, qkvl + g);
    }
    auto load_kv = [&](int kt, int st) {
        int k0 = kt << 7;
        uint32_t base = sb + 2*FTS + st*(4*FTS);
        for (int i = tid; i < 128*8; i += 256) {
            int r = i >> 3, c = i & 7;
            size_t gK = (rowbase + k0 + r) * QKVN + hoff + 768 + c*8;
            uint32_t dst = base + r*144 + c*16;
            cpasync16(dst,          qkvh + gK);
            cpasync16(dst + FTS,    qkvl + gK);
            cpasync16(dst + 2*FTS,  qkvh + gK + 768);
            cpasync16(dst + 3*FTS,  qkvl + gK + 768);
        }
    };
    load_kv(0, 0);
    asm volatile("cp.async.commit_group;" ::: "memory");

    uint32_t Qh[4][4], Ql[4][4];
    float accpv[8][4];
    #pragma unroll
    for (int i = 0; i < 8; i++)
        #pragma unroll
        for (int j = 0; j < 4; j++) accpv[i][j] = 0.f;
    float m0 = -1e30f, m1 = -1e30f, l0 = 0.f, l1 = 0.f;
    int r0 = lane >> 2;
    bool qfrag = false;

    for (int kt = 0; kt < 4; kt++) {
        int st = kt & 1;
        int k0 = kt << 7;
        asm volatile("cp.async.wait_group 0;" ::: "memory");
        __syncthreads();
        if (tid < 255) {
            int ridx = tid + k0 - q0 + 384;
            sbias[tid] = relb[(size_t)ridx * H_ + h];
        }
        if (kt < 3) {
            load_kv(kt + 1, st ^ 1);
            asm volatile("cp.async.commit_group;" ::: "memory");
        }
        if (!qfrag) {
            qfrag = true;
            uint32_t qa = sb + (wid*16 + (lane & 15))*144 + ((lane >> 4) << 4);
            #pragma unroll
            for (int kc = 0; kc < 4; kc++) {
                ldsm4(Qh[kc], qa + kc*32);
                ldsm4(Ql[kc], qa + FTS + kc*32);
            }
        }
        // ---- scores S[16q x 128k] per warp (3-pass) ----
        float sacc[16][4];
        #pragma unroll
        for (int i = 0; i < 16; i++)
            #pragma unroll
            for (int j = 0; j < 4; j++) sacc[i][j] = 0.f;
        uint32_t kbase = sb + 2*FTS + st*(4*FTS);
        uint32_t koff = (uint32_t)(((lane & 7) + ((lane >> 4) << 3))*144)
                      + ((((uint32_t)lane >> 3) & 1) << 4);
        #pragma unroll
        for (int np = 0; np < 8; np++) {
            #pragma unroll
            for (int kc = 0; kc < 4; kc++) {
                uint32_t kh4[4], kl4[4];
                uint32_t ka = kbase + np*(16*144) + koff + kc*32;
                ldsm4(kh4, ka);
                ldsm4(kl4, ka + FTS);
                mma16816(sacc[2*np],   Qh[kc], &kh4[0]);
                mma16816(sacc[2*np+1], Qh[kc], &kh4[2]);
                mma16816(sacc[2*np],   Qh[kc], &kl4[0]);
                mma16816(sacc[2*np+1], Qh[kc], &kl4[2]);
                mma16816(sacc[2*np],   Ql[kc], &kh4[0]);
                mma16816(sacc[2*np+1], Ql[kc], &kh4[2]);
            }
        }
        __syncthreads();  // sbias visible
        // ---- bias + online softmax ----
        int coff = 127 - wid*16;
        float mt0 = -1e30f, mt1 = -1e30f;
        #pragma unroll
        for (int nt = 0; nt < 16; nt++) {
            int col = nt*8 + ((lane & 3) << 1);
            int i0 = col + coff - r0;
            float s0 = fmaf(sacc[nt][0], 0.125f, sbias[i0]);
            float s1 = fmaf(sacc[nt][1], 0.125f, sbias[i0 + 1]);
            float s2 = fmaf(sacc[nt][2], 0.125f, sbias[i0 - 8]);
            float s3 = fmaf(sacc[nt][3], 0.125f, sbias[i0 - 7]);
            sacc[nt][0] = s0; sacc[nt][1] = s1;
            sacc[nt][2] = s2; sacc[nt][3] = s3;
            mt0 = fmaxf(mt0, fmaxf(s0, s1));
            mt1 = fmaxf(mt1, fmaxf(s2, s3));
        }
        #pragma unroll
        for (int o = 1; o < 4; o <<= 1) {
            mt0 = fmaxf(mt0, __shfl_xor_sync(0xffffffffu, mt0, o));
            mt1 = fmaxf(mt1, __shfl_xor_sync(0xffffffffu, mt1, o));
        }
        float mn0 = fmaxf(m0, mt0), mn1 = fmaxf(m1, mt1);
        float cr0 = __expf(m0 - mn0), cr1 = __expf(m1 - mn1);
        m0 = mn0; m1 = mn1;
        float rs0 = 0.f, rs1 = 0.f;
        #pragma unroll
        for (int nt = 0; nt < 16; nt++) {
            float p0 = __expf(sacc[nt][0] - mn0);
            float p1 = __expf(sacc[nt][1] - mn0);
            float p2 = __expf(sacc[nt][2] - mn1);
            float p3 = __expf(sacc[nt][3] - mn1);
            sacc[nt][0] = p0; sacc[nt][1] = p1;
            sacc[nt][2] = p2; sacc[nt][3] = p3;
            rs0 += p0 + p1; rs1 += p2 + p3;
        }
        #pragma unroll
        for (int o = 1; o < 4; o <<= 1) {
            rs0 += __shfl_xor_sync(0xffffffffu, rs0, o);
            rs1 += __shfl_xor_sync(0xffffffffu, rs1, o);
        }
        l0 = l0*cr0 + rs0; l1 = l1*cr1 + rs1;
        #pragma unroll
        for (int nd = 0; nd < 8; nd++) {
            accpv[nd][0] *= cr0; accpv[nd][1] *= cr0;
            accpv[nd][2] *= cr1; accpv[nd][3] *= cr1;
        }
        // ---- PV (3-pass) ----
        uint32_t vbase = kbase + 2*FTS;
        uint32_t voff = (uint32_t)((lane & 15)*144) + (((uint32_t)lane >> 4) << 4);
        #pragma unroll
        for (int kc2 = 0; kc2 < 8; kc2++) {
            uint32_t Pha[4], Pla[4];
            split2(sacc[2*kc2][0],   sacc[2*kc2][1],   Pha[0], Pla[0]);
            split2(sacc[2*kc2][2],   sacc[2*kc2][3],   Pha[1], Pla[1]);
            split2(sacc[2*kc2+1][0], sacc[2*kc2+1][1], Pha[2], Pla[2]);
            split2(sacc[2*kc2+1][2], sacc[2*kc2+1][3], Pha[3], Pla[3]);
            #pragma unroll
            for (int nd = 0; nd < 4; nd++) {
                uint32_t vh4[4], vl4[4];
                uint32_t va = vbase + kc2*(16*144) + voff + nd*32;
                ldsm4t(vh4, va);
                ldsm4t(vl4, va + FTS);
                mma16816(accpv[2*nd],   Pha, &vh4[0]);
                mma16816(accpv[2*nd+1], Pha, &vh4[2]);
                mma16816(accpv[2*nd],   Pha, &vl4[0]);
                mma16816(accpv[2*nd+1], Pha, &vl4[2]);
                mma16816(accpv[2*nd],   Pla, &vh4[0]);
                mma16816(accpv[2*nd+1], Pla, &vh4[2]);
            }
        }
        __syncthreads();
    }
    // ---- epilogue: ctx = accpv / l, hi/lo split ----
    float inv0 = 1.f / l0, inv1 = 1.f / l1;
    size_t row = rowbase + q0 + wid*16 + r0;
    #pragma unroll
    for (int nd = 0; nd < 8; nd++) {
        int col = hoff + nd*8 + ((lane & 3) << 1);
        uint32_t hp, lp;
        split2(accpv[nd][0]*inv0, accpv[nd][1]*inv0, hp, lp);
        *(uint32_t*)(cxh + row*D_ + col) = hp;
        *(uint32_t*)(cxl + row*D_ + col) = lp;
        split2(accpv[nd][2]*inv1, accpv[nd][3]*inv1, hp, lp);
        *(uint32_t*)(cxh + (row+8)*D_ + col) = hp;
        *(uint32_t*)(cxl + (row+8)*D_ + col) = lp;
    }
}

// ---------------- x = LayerNorm(x + t); writes fp32 + hi/lo -----------------
__global__ __launch_bounds__(256) void add_ln(
    float* __restrict__ x, const float* __restrict__ t,
    const float* __restrict__ g, const float* __restrict__ bb,
    bf16* __restrict__ xh, bf16* __restrict__ xl)
{
    int row = blockIdx.x, tid = threadIdx.x;
    size_t base = (size_t)row * D_;
    float v[4]; float s = 0.f;
    bool on = tid < 192;
    if (on) {
        float4 a = *(const float4*)(x + base + tid*4);
        float4 c = *(const float4*)(t + base + tid*4);
        v[0] = a.x + c.x; v[1] = a.y + c.y; v[2] = a.z + c.z; v[3] = a.w + c.w;
        s = v[0] + v[1] + v[2] + v[3];
    } else { v[0] = v[1] = v[2] = v[3] = 0.f; }
    float mean = block_sum(s) * (1.f/(float)D_);
    float ss = 0.f;
    if (on) {
        #pragma unroll
        for (int i = 0; i < 4; i++) { float d = v[i]-mean; ss += d*d; }
    }
    float rstd = rsqrtf(block_sum(ss) * (1.f/(float)D_) + 1e-5f);
    if (on) {
        float4 gg = *(const float4*)(g + tid*4);
        float4 bv = *(const float4*)(bb + tid*4);
        float o0 = (v[0]-mean)*rstd*gg.x + bv.x;
        float o1 = (v[1]-mean)*rstd*gg.y + bv.y;
        float o2 = (v[2]-mean)*rstd*gg.z + bv.z;
        float o3 = (v[3]-mean)*rstd*gg.w + bv.w;
        *(float4*)(x + base + tid*4) = make_float4(o0, o1, o2, o3);
        uint32_t h01, l01, h23, l23;
        split2(o0, o1, h01, l01); split2(o2, o3, h23, l23);
        *(uint2*)(xh + base + tid*4) = make_uint2(h01, h23);
        *(uint2*)(xl + base + tid*4) = make_uint2(l01, l23);
    }
}

// ---------------- head ------------------------------------------------------
__global__ __launch_bounds__(256) void meanpool(
    const float* __restrict__ x, float* __restrict__ pool)
{
    int d = blockIdx.x*256 + threadIdx.x;
    int b = blockIdx.y;
    float s = 0.f;
    for (int t = 0; t < S_; t++) s += x[((size_t)b*S_ + t)*D_ + d];
    pool[b*D_ + d] = s * (1.f/(float)S_);
}
__global__ __launch_bounds__(256) void fc1(
    const float* __restrict__ pool, const float* __restrict__ w,
    const float* __restrict__ bias, float* __restrict__ out)
{
    int idx = blockIdx.x*256 + threadIdx.x;
    int b = idx / (D_/2), j = idx % (D_/2);
    float s = bias[j];
    for (int d = 0; d < D_; d++) s = fmaf(pool[b*D_ + d], w[d*(D_/2) + j], s);
    out[idx] = fmaxf(s, 0.f);
}
__global__ __launch_bounds__(256) void fc2(
    const float* __restrict__ h, const float* __restrict__ w,
    const float* __restrict__ bias, float* __restrict__ out)
{
    int idx = blockIdx.x*256 + threadIdx.x;
    if (idx >= B_*NC_) return;
    int b = idx / NC_, c = idx % NC_;
    float s = bias[c];
    for (int j = 0; j < D_/2; j++) s = fmaf(h[b*(D_/2) + j], w[j*NC_ + c], s);
    out[idx] = s;
}

// ---------------- launch ----------------------------------------------------
extern "C" void kernel_launch(void* const* d_in, const int* in_sizes, int n_in,
                              void* d_out, int out_size)
{
    const int*   ids  = (const int*)  d_in[0];
    const float* emb  = (const float*)d_in[1];
    const float* wq   = (const float*)d_in[2];
    const float* bq   = (const float*)d_in[3];
    const float* wk   = (const float*)d_in[4];
    const float* bk   = (const float*)d_in[5];
    const float* wv   = (const float*)d_in[6];
    const float* bv   = (const float*)d_in[7];
    const float* wo   = (const float*)d_in[8];
    const float* bo   = (const float*)d_in[9];
    const float* relb = (const float*)d_in[10];
    const float* w1   = (const float*)d_in[11];
    const float* b1   = (const float*)d_in[12];
    const float* w2   = (const float*)d_in[13];
    const float* b2   = (const float*)d_in[14];
    const float* l1g  = (const float*)d_in[15];
    const float* l1b  = (const float*)d_in[16];
    const float* l2g  = (const float*)d_in[17];
    const float* l2b  = (const float*)d_in[18];
    const float* cw1  = (const float*)d_in[19];
    const float* cb1  = (const float*)d_in[20];
    const float* cw2  = (const float*)d_in[21];
    const float* cb2  = (const float*)d_in[22];

    cudaFuncSetAttribute(gemm_mma,   cudaFuncAttributeMaxDynamicSharedMemorySize, GSMEM);
    cudaFuncSetAttribute(flash_attn, cudaFuncAttributeMaxDynamicSharedMemorySize, FSMEM);

    float *x, *t, *pool, *chd, *bqkv;
    bf16 *xh,*xl,*qkvh,*qkvl,*cxh,*cxl,*fh,*fl;
    bf16 *wqkvh,*wqkvl,*woh,*wol,*w1h,*w1l,*w2h,*w2l;
    cudaGetSymbolAddress((void**)&x,    g_x);
    cudaGetSymbolAddress((void**)&t,    g_t);
    cudaGetSymbolAddress((void**)&pool, g_pool);
    cudaGetSymbolAddress((void**)&chd,  g_chd);
    cudaGetSymbolAddress((void**)&bqkv, g_bqkv);
    cudaGetSymbolAddress((void**)&xh,   g_xh);
    cudaGetSymbolAddress((void**)&xl,   g_xl);
    cudaGetSymbolAddress((void**)&qkvh, g_qkvh);
    cudaGetSymbolAddress((void**)&qkvl, g_qkvl);
    cudaGetSymbolAddress((void**)&cxh,  g_cxh);
    cudaGetSymbolAddress((void**)&cxl,  g_cxl);
    cudaGetSymbolAddress((void**)&fh,   g_fh);
    cudaGetSymbolAddress((void**)&fl,   g_fl);
    cudaGetSymbolAddress((void**)&wqkvh,g_wqkvh);
    cudaGetSymbolAddress((void**)&wqkvl,g_wqkvl);
    cudaGetSymbolAddress((void**)&woh,  g_woh);
    cudaGetSymbolAddress((void**)&wol,  g_wol);
    cudaGetSymbolAddress((void**)&w1h,  g_w1h);
    cudaGetSymbolAddress((void**)&w1l,  g_w1l);
    cudaGetSymbolAddress((void**)&w2h,  g_w2h);
    cudaGetSymbolAddress((void**)&w2l,  g_w2l);

    embed_kernel<<<ROWS, 256>>>(ids, emb, x, xh, xl);
    wprep_qkv3<<<dim3(D_/32, D_/32, L_*3), 256>>>(wq, wk, wv, wqkvh, wqkvl);
    wprep_l<<<dim3(D_/32, D_/32, L_), 256>>>(wo, woh, wol, D_, D_);
    wprep_l<<<dim3(DFF_/32, D_/32, L_), 256>>>(w1, w1h, w1l, D_, DFF_);
    wprep_l<<<dim3(D_/32, DFF_/32, L_), 256>>>(w2, w2h, w2l, DFF_, D_);
    bias_pack<<<(L_*QKVN + 255)/256, 256>>>(bq, bk, bv, bqkv);

    dim3 gQKV(QKVN/128, ROWS/128);
    dim3 gDD(D_/128, ROWS/128);
    dim3 gF1(DFF_/128, ROWS/128);

    for (int l = 0; l < L_; l++) {
        gemm_mma<<<gQKV, 256, GSMEM>>>(xh, xl, D_,
            wqkvh + (size_t)l*QKVN*D_, wqkvl + (size_t)l*QKVN*D_, D_,
            bqkv + (size_t)l*QKVN, nullptr, qkvh, qkvl, QKVN, QKVN, D_, 1);

        flash_attn<<<dim3(S_/128, BH_), 256, FSMEM>>>(
            qkvh, qkvl, relb + (size_t)l*(2*S_-1)*H_, cxh, cxl);

        gemm_mma<<<gDD, 256, GSMEM>>>(cxh, cxl, D_,
            woh + (size_t)l*D_*D_, wol + (size_t)l*D_*D_, D_,
            bo + l*D_, t, nullptr, nullptr, D_, D_, D_, 0);
        add_ln<<<ROWS, 256>>>(x, t, l1g + l*D_, l1b + l*D_, xh, xl);

        gemm_mma<<<gF1, 256, GSMEM>>>(xh, xl, D_,
            w1h + (size_t)l*D_*DFF_, w1l + (size_t)l*D_*DFF_, D_,
            b1 + l*DFF_, nullptr, fh, fl, DFF_, DFF_, D_, 2);
        gemm_mma<<<gDD, 256, GSMEM>>>(fh, fl, DFF_,
            w2h + (size_t)l*DFF_*D_, w2l + (size_t)l*DFF_*D_, DFF_,
            b2 + l*D_, t, nullptr, nullptr, D_, D_, DFF_, 0);
        add_ln<<<ROWS, 256>>>(x, t, l2g + l*D_, l2b + l*D_, xh, xl);
    }

    meanpool<<<dim3(D_/256, B_), 256>>>(x, pool);
    fc1<<<(B_*(D_/2))/256, 256>>>(pool, cw1, cb1, chd);
    fc2<<<(B_*NC_ + 255)/256, 256>>>(chd, cw2, cb2, (float*)d_out);
}